// round 9
// baseline (speedup 1.0000x reference)
#include <cuda_runtime.h>
#include <cuda_fp16.h>
#include <mma.h>
#include <math.h>

using namespace nvcuda;

#define NN 100000
#define EE 1600000
#define MM (EE + NN)
#define NB 49            // ceil(NN / 2048)
#define EPSV 1e-5f

// ---------------- scratch (static device allocations; no cudaMalloc) ----------------
__device__ int   g_is64 = 1;        // detection only ever clears -> stable across replays
__device__ int   g_deg[NN];
__device__ float g_dinv[NN];
__device__ int   g_start[NN];
__device__ int   g_cursor[NN];
__device__ int   g_tilesum[NB];
__device__ int2  g_cw[MM];          // (src, norm-bits) per CSR slot
__device__ float g_s[NN];           // row sums of normalized adjacency
__device__ __align__(16) float g_h[NN * 64];      // GEMM out: fp16 (L1/2) or fp32 (L3)
__device__ __align__(16) float g_agg[NN * 64];    // aggregation output (fp32)
__device__ float g_stats1[128];     // [sum(64), sumsq(64)]
__device__ float g_stats2[128];
__device__ float g_W2f[64 * 64];    // BN1-folded W2
__device__ float g_W3f[64 * 40];    // BN2-folded W3
__device__ float g_t2[64];
__device__ float g_t3[64];
__device__ __align__(16) float g_zero64[64];

// ---------------- graph init + sampled dtype detect ----------------
__global__ void k_init(const long long* __restrict__ p) {
    int i = blockIdx.x * blockDim.x + threadIdx.x;
    if (i < NN) { g_deg[i] = 1; g_s[i] = 0.f; }      // self-loop
    if (i < 128) { g_stats1[i] = 0.f; g_stats2[i] = 0.f; }
    if (i < 64) g_zero64[i] = 0.f;
    if (i < 65536) {
        long long v = p[(size_t)i * 24];             // max idx < EE int64 slots
        if (v < 0 || v >= NN) g_is64 = 0;            // only writes 0: race-free
    }
}

__device__ __forceinline__ long long edge_at(const void* ei, int idx) {
    if (g_is64) return ((const long long*)ei)[idx];
    return (long long)((const int*)ei)[idx];
}

__global__ void k_degree(const void* __restrict__ ei) {
    int i = blockIdx.x * blockDim.x + threadIdx.x;
    if (i >= EE) return;
    long long d = edge_at(ei, EE + i);
    if ((unsigned long long)d < (unsigned long long)NN)
        atomicAdd(&g_deg[(int)d], 1);
}

__global__ void k_scanA() {   // block-tile sums (tile = 2048) + fused dinv
    int base = blockIdx.x * 2048;
    int s = 0;
    for (int i = threadIdx.x; i < 2048; i += 256) {
        int idx = base + i;
        if (idx < NN) {
            int d = g_deg[idx];
            s += d;
            g_dinv[idx] = rsqrtf((float)d);
        }
    }
    __shared__ int sh[256];
    sh[threadIdx.x] = s;
    __syncthreads();
    for (int o = 128; o > 0; o >>= 1) {
        if (threadIdx.x < o) sh[threadIdx.x] += sh[threadIdx.x + o];
        __syncthreads();
    }
    if (threadIdx.x == 0) g_tilesum[blockIdx.x] = sh[0];
}

// intra-tile exclusive scan -> start/cursor; tile offset computed in-kernel
__global__ void k_scanC() {
    int tid = threadIdx.x;
    __shared__ int s_off;
    if (tid < 32) {
        int v = 0;
        for (int j = tid; j < blockIdx.x; j += 32) v += g_tilesum[j];
        #pragma unroll
        for (int o = 16; o > 0; o >>= 1) v += __shfl_xor_sync(0xffffffffu, v, o);
        if (tid == 0) s_off = v;
    }
    int base = blockIdx.x * 2048 + tid * 8;
    int loc[8];
    int s = 0;
    #pragma unroll
    for (int j = 0; j < 8; j++) {
        int idx = base + j;
        int d = (idx < NN) ? g_deg[idx] : 0;
        loc[j] = s; s += d;
    }
    __shared__ int sh[256];
    sh[tid] = s;
    __syncthreads();
    int run = s;
    for (int o = 1; o < 256; o <<= 1) {
        int v = (tid >= o) ? sh[tid - o] : 0;
        __syncthreads();
        sh[tid] += v;
        __syncthreads();
    }
    int off = s_off + sh[tid] - run;
    #pragma unroll
    for (int j = 0; j < 8; j++) {
        int idx = base + j;
        if (idx < NN) { int p = off + loc[j]; g_start[idx] = p; g_cursor[idx] = p; }
    }
}

// CSR fill + fused row-sum (s_d accumulated via float atomics).
__global__ void k_fill(const void* __restrict__ ei) {
    int i = blockIdx.x * blockDim.x + threadIdx.x;
    if (i >= MM) return;
    int s, d;
    if (i < EE) {
        long long ls = edge_at(ei, i);
        long long ld = edge_at(ei, EE + i);
        if ((unsigned long long)ls >= (unsigned long long)NN) return;
        if ((unsigned long long)ld >= (unsigned long long)NN) return;
        s = (int)ls; d = (int)ld;
    } else {
        s = i - EE; d = s;
    }
    float w = g_dinv[s] * g_dinv[d];
    int pos = atomicAdd(&g_cursor[d], 1);
    g_cw[pos] = make_int2(s, __float_as_int(w));
    atomicAdd(&g_s[d], w);
}

// ---------------- tensor-core GEMM: out[N x NCOUT] = in[N x 64] @ W[64 x NCOUT] ----
// fp16 operands, fp32 accumulate. 64x64 block tile, 8 warps x 2 m16n16k16 frags.
// W zero-padded to 64 cols when NCOUT < 64. Output fp16 (HOUT, stride 64) or fp32.
template <int NCOUT, bool HOUT>
__global__ void __launch_bounds__(256)
k_gemm_tc(const float* __restrict__ in, const float* __restrict__ W,
          void* __restrict__ out) {
    __shared__ __half As[64 * 72];
    __shared__ __half Bs[64 * 72];
    __shared__ float  Cs[64 * 72];
    int tid = threadIdx.x;
    int row0 = blockIdx.x * 64;

    // W [64 x NCOUT] -> Bs fp16, zero-pad cols to 64
    for (int i = tid; i < 64 * 64; i += 256) {
        int k = i >> 6, j = i & 63;
        float w = (j < NCOUT) ? W[k * NCOUT + j] : 0.f;
        Bs[k * 72 + j] = __float2half_rn(w);
    }
    // A rows -> As fp16 (fp32 -> fp16 on the fly)
    for (int i = tid; i < 64 * 16; i += 256) {
        int r = i >> 4, k4 = i & 15;
        int gr = row0 + r;
        float4 v = make_float4(0.f, 0.f, 0.f, 0.f);
        if (gr < NN) v = ((const float4*)(in + (size_t)gr * 64))[k4];
        __half2* dst = (__half2*)&As[r * 72 + k4 * 4];
        dst[0] = __floats2half2_rn(v.x, v.y);
        dst[1] = __floats2half2_rn(v.z, v.w);
    }
    __syncthreads();

    int wid = tid >> 5;
    int wr = wid >> 1, wc = wid & 1;     // 4 row-groups x 2 col-groups (each 16x32)
    wmma::fragment<wmma::accumulator, 16, 16, 16, float> c0, c1;
    wmma::fill_fragment(c0, 0.f);
    wmma::fill_fragment(c1, 0.f);
    #pragma unroll
    for (int kk = 0; kk < 4; kk++) {
        wmma::fragment<wmma::matrix_a, 16, 16, 16, __half, wmma::row_major> a;
        wmma::load_matrix_sync(a, &As[wr * 16 * 72 + kk * 16], 72);
        wmma::fragment<wmma::matrix_b, 16, 16, 16, __half, wmma::row_major> b;
        wmma::load_matrix_sync(b, &Bs[kk * 16 * 72 + wc * 32], 72);
        wmma::mma_sync(c0, a, b, c0);
        wmma::load_matrix_sync(b, &Bs[kk * 16 * 72 + wc * 32 + 16], 72);
        wmma::mma_sync(c1, a, b, c1);
    }
    wmma::store_matrix_sync(&Cs[wr * 16 * 72 + wc * 32], c0, 72, wmma::mem_row_major);
    wmma::store_matrix_sync(&Cs[wr * 16 * 72 + wc * 32 + 16], c1, 72, wmma::mem_row_major);
    __syncthreads();

    if (HOUT) {
        for (int i = tid; i < 64 * 16; i += 256) {
            int r = i >> 4, c4 = i & 15;
            int gr = row0 + r;
            if (gr < NN) {
                float4 v = *(float4*)&Cs[r * 72 + c4 * 4];
                __half2* o2 = (__half2*)((__half*)out + (size_t)gr * 64 + c4 * 4);
                o2[0] = __floats2half2_rn(v.x, v.y);
                o2[1] = __floats2half2_rn(v.z, v.w);
            }
        }
    } else {
        for (int i = tid; i < 64 * (NCOUT / 4); i += 256) {
            int r = i / (NCOUT / 4), c4 = i % (NCOUT / 4);
            int gr = row0 + r;
            if (gr < NN)
                *(float4*)&((float*)out)[(size_t)gr * NCOUT + c4 * 4] =
                    *(float4*)&Cs[r * 72 + c4 * 4];
        }
    }
}

// ---------------- aggregation (NC=64, fp16 h): quarter-warp uint4, 4 edges/iter ----------
__global__ void k_agg64h(const uint4* __restrict__ h4, const float* __restrict__ bias,
                         const float* __restrict__ t, float* __restrict__ out) {
    int wid  = (blockIdx.x * blockDim.x + threadIdx.x) >> 5;
    int lane = threadIdx.x & 31;
    if (wid >= NN) return;
    int q = lane >> 3, ql = lane & 7;
    int st = g_start[wid], en = st + g_deg[wid];
    float acc[8];
    #pragma unroll
    for (int i = 0; i < 8; i++) acc[i] = 0.f;

    #pragma unroll 2
    for (int e = st + q; e < en; e += 4) {
        int2 c = __ldg(&g_cw[e]);
        uint4 v = __ldg(h4 + (size_t)c.x * 8 + ql);   // 8 halves of the row
        float w = __int_as_float(c.y);
        float2 f;
        f = __half22float2(*(const __half2*)&v.x); acc[0] += w * f.x; acc[1] += w * f.y;
        f = __half22float2(*(const __half2*)&v.y); acc[2] += w * f.x; acc[3] += w * f.y;
        f = __half22float2(*(const __half2*)&v.z); acc[4] += w * f.x; acc[5] += w * f.y;
        f = __half22float2(*(const __half2*)&v.w); acc[6] += w * f.x; acc[7] += w * f.y;
    }
    #pragma unroll
    for (int i = 0; i < 8; i++) {
        acc[i] += __shfl_xor_sync(0xffffffffu, acc[i], 8);
        acc[i] += __shfl_xor_sync(0xffffffffu, acc[i], 16);
    }
    if (q == 0) {   // lanes 0-7 hold full sums for cols ql*8 .. ql*8+7
        float sd = g_s[wid];
        const float4* b4 = (const float4*)(bias + ql * 8);
        const float4* t4 = (const float4*)(t + ql * 8);
        float4 b0 = __ldg(b4), b1 = __ldg(b4 + 1);
        float4 t0 = __ldg(t4), t1 = __ldg(t4 + 1);
        float4 o0, o1;
        o0.x = acc[0] + b0.x + sd * t0.x;
        o0.y = acc[1] + b0.y + sd * t0.y;
        o0.z = acc[2] + b0.z + sd * t0.z;
        o0.w = acc[3] + b0.w + sd * t0.w;
        o1.x = acc[4] + b1.x + sd * t1.x;
        o1.y = acc[5] + b1.y + sd * t1.y;
        o1.z = acc[6] + b1.z + sd * t1.z;
        o1.w = acc[7] + b1.w + sd * t1.w;
        float4* op = (float4*)(out + (size_t)wid * 64 + ql * 8);
        op[0] = o0; op[1] = o1;
    }
}

// ---------------- aggregation (NC=40, fp32 h) + fused log_softmax ----------------
__global__ void k_agg40lsm(const float* __restrict__ h, const float* __restrict__ bias,
                           const float* __restrict__ t, float* __restrict__ emb,
                           float* __restrict__ out) {
    int wid  = (blockIdx.x * blockDim.x + threadIdx.x) >> 5;
    int lane = threadIdx.x & 31;
    if (wid >= NN) return;
    bool act = lane < 20;
    int ln = act ? lane : 0;                 // keep loads in-bounds for idle lanes
    const float2* h2 = (const float2*)h;     // row stride = 20 float2
    int e = g_start[wid], en = e + g_deg[wid];
    float ax = 0.f, ay = 0.f;
    while (e + 4 <= en) {
        int2 c0 = __ldg(&g_cw[e]);
        int2 c1 = __ldg(&g_cw[e + 1]);
        int2 c2 = __ldg(&g_cw[e + 2]);
        int2 c3 = __ldg(&g_cw[e + 3]);
        float2 v0 = __ldg(h2 + (size_t)c0.x * 20 + ln);
        float2 v1 = __ldg(h2 + (size_t)c1.x * 20 + ln);
        float2 v2 = __ldg(h2 + (size_t)c2.x * 20 + ln);
        float2 v3 = __ldg(h2 + (size_t)c3.x * 20 + ln);
        float w0 = __int_as_float(c0.y), w1 = __int_as_float(c1.y);
        float w2 = __int_as_float(c2.y), w3 = __int_as_float(c3.y);
        ax += w0 * v0.x; ay += w0 * v0.y;
        ax += w1 * v1.x; ay += w1 * v1.y;
        ax += w2 * v2.x; ay += w2 * v2.y;
        ax += w3 * v3.x; ay += w3 * v3.y;
        e += 4;
    }
    while (e < en) {
        int2 c = __ldg(&g_cw[e++]);
        float2 v = __ldg(h2 + (size_t)c.x * 20 + ln);
        float w = __int_as_float(c.y);
        ax += w * v.x; ay += w * v.y;
    }
    float sd = g_s[wid];
    float v0 = 0.f, v1 = 0.f;
    if (act) {
        int c = lane * 2;
        v0 = ax + bias[c]     + sd * t[c];
        v1 = ay + bias[c + 1] + sd * t[c + 1];
        ((float2*)emb)[(size_t)wid * 20 + lane] = make_float2(v0, v1);
    }
    float m = act ? fmaxf(v0, v1) : -3.4e38f;
    #pragma unroll
    for (int o = 16; o > 0; o >>= 1) m = fmaxf(m, __shfl_xor_sync(0xffffffffu, m, o));
    float s = act ? (__expf(v0 - m) + __expf(v1 - m)) : 0.f;
    #pragma unroll
    for (int o = 16; o > 0; o >>= 1) s += __shfl_xor_sync(0xffffffffu, s, o);
    float lse = m + logf(s);
    if (act)
        ((float2*)out)[(size_t)wid * 20 + lane] = make_float2(v0 - lse, v1 - lse);
}

// ---------------- BN column stats (sum, sumsq) ----------------
__global__ void k_stats(const float* __restrict__ a, float* __restrict__ st) {
    int col = threadIdx.x & 63, sub = threadIdx.x >> 6;
    float s = 0.f, q = 0.f;
    for (int r = blockIdx.x * 4 + sub; r < NN; r += gridDim.x * 4) {
        float v = a[(size_t)r * 64 + col];
        s += v; q += v * v;
    }
    __shared__ float shs[256], shq[256];
    shs[threadIdx.x] = s; shq[threadIdx.x] = q;
    __syncthreads();
    if (sub == 0) {
        s = shs[col] + shs[col + 64] + shs[col + 128] + shs[col + 192];
        q = shq[col] + shq[col + 64] + shq[col + 128] + shq[col + 192];
        atomicAdd(&st[col], s);
        atomicAdd(&st[col + 64], q);
    }
}

// ---------------- fold BN into next layer's weights ----------------
template <int NCN>
__global__ void k_fold(const float* __restrict__ W, const float* __restrict__ g,
                       const float* __restrict__ be, const float* __restrict__ st,
                       float* __restrict__ Wf, float* __restrict__ t) {
    __shared__ float a[64], c[64];
    int tid = threadIdx.x;
    if (tid < 64) {
        float mean = st[tid] * (1.f / NN);
        float var  = st[tid + 64] * (1.f / NN) - mean * mean;
        float ai = g[tid] * rsqrtf(var + EPSV);
        a[tid] = ai;
        c[tid] = be[tid] - mean * ai;
    }
    __syncthreads();
    for (int i = tid; i < 64 * NCN; i += 256) Wf[i] = a[i / NCN] * W[i];
    if (tid < NCN) {
        float tv = 0.f;
        #pragma unroll
        for (int k = 0; k < 64; k++) tv += c[k] * W[k * NCN + tid];
        t[tid] = tv;
    }
}

// ---------------- launcher ----------------
extern "C" void kernel_launch(void* const* d_in, const int* in_sizes, int n_in,
                              void* d_out, int out_size) {
    const float* x   = (const float*)d_in[0];
    const void*  ei  = d_in[1];                 // int32 or int64, detected on device
    const float* W1  = (const float*)d_in[2];
    const float* b1  = (const float*)d_in[3];
    const float* W2  = (const float*)d_in[4];
    const float* b2  = (const float*)d_in[5];
    const float* W3  = (const float*)d_in[6];
    const float* b3  = (const float*)d_in[7];
    const float* g1  = (const float*)d_in[8];
    const float* be1 = (const float*)d_in[9];
    const float* g2  = (const float*)d_in[10];
    const float* be2 = (const float*)d_in[11];
    float* out = (float*)d_out;

    float *hP, *aP, *W2fP, *W3fP, *t2P, *t3P, *z64P, *s1P, *s2P;
    cudaGetSymbolAddress((void**)&hP,   g_h);
    cudaGetSymbolAddress((void**)&aP,   g_agg);
    cudaGetSymbolAddress((void**)&W2fP, g_W2f);
    cudaGetSymbolAddress((void**)&W3fP, g_W3f);
    cudaGetSymbolAddress((void**)&t2P,  g_t2);
    cudaGetSymbolAddress((void**)&t3P,  g_t3);
    cudaGetSymbolAddress((void**)&z64P, g_zero64);
    cudaGetSymbolAddress((void**)&s1P,  g_stats1);
    cudaGetSymbolAddress((void**)&s2P,  g_stats2);

    // output layout: (out, emb) concatenated
    float* emb = (out_size >= 2 * NN * 40) ? (out + NN * 40) : aP;

    // graph build (single stream; R7 showed forked capture regresses)
    k_init  <<<(NN + 255) / 256, 256>>>((const long long*)ei);
    k_degree<<<(EE + 255) / 256, 256>>>(ei);
    k_scanA <<<NB, 256>>>();
    k_scanC <<<NB, 256>>>();
    k_fill  <<<(MM + 255) / 256, 256>>>(ei);

    // layer 1 (tensor-core GEMM, h in fp16)
    k_gemm_tc<64, true><<<(NN + 63) / 64, 256>>>(x, W1, hP);
    k_agg64h  <<<(NN + 7) / 8, 256>>>((const uint4*)hP, b1, z64P, aP);
    k_stats   <<<256, 256>>>(aP, s1P);
    k_fold<64><<<1, 256>>>(W2, g1, be1, s1P, W2fP, t2P);

    // layer 2 (BN1 folded into W2, h in fp16)
    k_gemm_tc<64, true><<<(NN + 63) / 64, 256>>>(aP, W2fP, hP);
    k_agg64h  <<<(NN + 7) / 8, 256>>>((const uint4*)hP, b2, t2P, aP);
    k_stats   <<<256, 256>>>(aP, s2P);
    k_fold<40><<<1, 256>>>(W3, g2, be2, s2P, W3fP, t3P);

    // layer 3 (BN2 folded into W3, fp32 out) -> emb + fused log_softmax -> out
    k_gemm_tc<40, false><<<(NN + 63) / 64, 256>>>(aP, W3fP, hP);
    k_agg40lsm<<<(NN + 7) / 8, 256>>>(hP, b3, t3P, emb, out);
}

// round 10
// speedup vs baseline: 1.2118x; 1.2118x over previous
#include <cuda_runtime.h>
#include <cuda_fp16.h>
#include <math.h>

#define NN 100000
#define EE 1600000
#define MM (EE + NN)
#define NB 49            // ceil(NN / 2048)
#define EPSV 1e-5f

// ---------------- scratch (static device allocations; no cudaMalloc) ----------------
__device__ int   g_is64 = 1;        // detection only ever clears -> stable across replays
__device__ int   g_deg[NN];
__device__ float g_dinv[NN];
__device__ int   g_start[NN];
__device__ int   g_cursor[NN];
__device__ int   g_tilesum[NB];
__device__ int2  g_cw[MM];          // (src, norm-bits) per CSR slot
__device__ float g_s[NN];           // row sums of normalized adjacency
__device__ __align__(16) float g_h[NN * 64];      // GEMM out: fp16 (L1/2) or fp32 (L3)
__device__ __align__(16) float g_agg[NN * 64];    // aggregation output (fp32)
__device__ float g_stats1[128];     // [sum(64), sumsq(64)]
__device__ float g_stats2[128];
__device__ float g_W2f[64 * 64];    // BN1-folded W2
__device__ __align__(16) float g_W3f[64 * 40];    // BN2-folded W3
__device__ float g_t2[64];
__device__ __align__(16) float g_t3[64];
__device__ __align__(16) float g_zero64[64];

// ---------------- graph init + sampled dtype detect ----------------
__global__ void k_init(const long long* __restrict__ p) {
    int i = blockIdx.x * blockDim.x + threadIdx.x;
    if (i < NN) { g_deg[i] = 1; g_s[i] = 0.f; }      // self-loop
    if (i < 128) { g_stats1[i] = 0.f; g_stats2[i] = 0.f; }
    if (i < 64) g_zero64[i] = 0.f;
    if (i < 65536) {
        long long v = p[(size_t)i * 24];             // max idx < EE int64 slots
        if (v < 0 || v >= NN) g_is64 = 0;            // only writes 0: race-free
    }
}

__device__ __forceinline__ long long edge_at(const void* ei, int idx) {
    if (g_is64) return ((const long long*)ei)[idx];
    return (long long)((const int*)ei)[idx];
}

__global__ void k_degree(const void* __restrict__ ei) {
    int i = blockIdx.x * blockDim.x + threadIdx.x;
    if (i >= EE) return;
    long long d = edge_at(ei, EE + i);
    if ((unsigned long long)d < (unsigned long long)NN)
        atomicAdd(&g_deg[(int)d], 1);
}

__global__ void k_scanA() {   // block-tile sums (tile = 2048) + fused dinv
    int base = blockIdx.x * 2048;
    int s = 0;
    for (int i = threadIdx.x; i < 2048; i += 256) {
        int idx = base + i;
        if (idx < NN) {
            int d = g_deg[idx];
            s += d;
            g_dinv[idx] = rsqrtf((float)d);
        }
    }
    __shared__ int sh[256];
    sh[threadIdx.x] = s;
    __syncthreads();
    for (int o = 128; o > 0; o >>= 1) {
        if (threadIdx.x < o) sh[threadIdx.x] += sh[threadIdx.x + o];
        __syncthreads();
    }
    if (threadIdx.x == 0) g_tilesum[blockIdx.x] = sh[0];
}

// intra-tile exclusive scan -> start/cursor; tile offset computed in-kernel
__global__ void k_scanC() {
    int tid = threadIdx.x;
    __shared__ int s_off;
    if (tid < 32) {
        int v = 0;
        for (int j = tid; j < blockIdx.x; j += 32) v += g_tilesum[j];
        #pragma unroll
        for (int o = 16; o > 0; o >>= 1) v += __shfl_xor_sync(0xffffffffu, v, o);
        if (tid == 0) s_off = v;
    }
    int base = blockIdx.x * 2048 + tid * 8;
    int loc[8];
    int s = 0;
    #pragma unroll
    for (int j = 0; j < 8; j++) {
        int idx = base + j;
        int d = (idx < NN) ? g_deg[idx] : 0;
        loc[j] = s; s += d;
    }
    __shared__ int sh[256];
    sh[tid] = s;
    __syncthreads();
    int run = s;
    for (int o = 1; o < 256; o <<= 1) {
        int v = (tid >= o) ? sh[tid - o] : 0;
        __syncthreads();
        sh[tid] += v;
        __syncthreads();
    }
    int off = s_off + sh[tid] - run;
    #pragma unroll
    for (int j = 0; j < 8; j++) {
        int idx = base + j;
        if (idx < NN) { int p = off + loc[j]; g_start[idx] = p; g_cursor[idx] = p; }
    }
}

// CSR fill + fused row-sum (s_d accumulated via float atomics).
__global__ void k_fill(const void* __restrict__ ei) {
    int i = blockIdx.x * blockDim.x + threadIdx.x;
    if (i >= MM) return;
    int s, d;
    if (i < EE) {
        long long ls = edge_at(ei, i);
        long long ld = edge_at(ei, EE + i);
        if ((unsigned long long)ls >= (unsigned long long)NN) return;
        if ((unsigned long long)ld >= (unsigned long long)NN) return;
        s = (int)ls; d = (int)ld;
    } else {
        s = i - EE; d = s;
    }
    float w = g_dinv[s] * g_dinv[d];
    int pos = atomicAdd(&g_cursor[d], 1);
    g_cw[pos] = make_int2(s, __float_as_int(w));
    atomicAdd(&g_s[d], w);
}

// ---------------- GEMM: out[N x NC] = in[N x 64] @ W[64 x NC] ----------------
// fp32 compute; output fp16 (HOUT, row stride 64 halves) or fp32.
// blockDim must be (NC/4)*16; block tile = 64 rows x NC cols.
template <int NC, bool HOUT>
__global__ void k_gemm(const float* __restrict__ in, const float* __restrict__ W,
                       void* __restrict__ out) {
    __shared__ float XsT[64 * 68];   // [k][row], padded
    __shared__ float Ws[64 * NC];    // [k][j]
    const int nth = (NC / 4) * 16;
    int tid = threadIdx.x;
    int row0 = blockIdx.x * 64;

    for (int i = tid; i < 64 * NC / 4; i += nth)
        ((float4*)Ws)[i] = ((const float4*)W)[i];

    for (int i = tid; i < 64 * 16; i += nth) {
        int r = i & 63, k4 = i >> 6;
        int gr = row0 + r;
        float4 v = make_float4(0.f, 0.f, 0.f, 0.f);
        if (gr < NN) v = ((const float4*)(in + (size_t)gr * 64))[k4];
        XsT[(k4 * 4 + 0) * 68 + r] = v.x;
        XsT[(k4 * 4 + 1) * 68 + r] = v.y;
        XsT[(k4 * 4 + 2) * 68 + r] = v.z;
        XsT[(k4 * 4 + 3) * 68 + r] = v.w;
    }
    __syncthreads();

    int tc = tid % (NC / 4), tr = tid / (NC / 4);
    int c0 = tc * 4, r0 = tr * 4;
    float acc[4][4];
    #pragma unroll
    for (int i = 0; i < 4; i++)
        #pragma unroll
        for (int j = 0; j < 4; j++) acc[i][j] = 0.f;

    #pragma unroll 8
    for (int k = 0; k < 64; k++) {
        float4 b = *(const float4*)&Ws[k * NC + c0];
        float4 a = *(const float4*)&XsT[k * 68 + r0];
        acc[0][0] += a.x * b.x; acc[0][1] += a.x * b.y; acc[0][2] += a.x * b.z; acc[0][3] += a.x * b.w;
        acc[1][0] += a.y * b.x; acc[1][1] += a.y * b.y; acc[1][2] += a.y * b.z; acc[1][3] += a.y * b.w;
        acc[2][0] += a.z * b.x; acc[2][1] += a.z * b.y; acc[2][2] += a.z * b.z; acc[2][3] += a.z * b.w;
        acc[3][0] += a.w * b.x; acc[3][1] += a.w * b.y; acc[3][2] += a.w * b.z; acc[3][3] += a.w * b.w;
    }

    #pragma unroll
    for (int i = 0; i < 4; i++) {
        int gr = row0 + r0 + i;
        if (gr < NN) {
            if (HOUT) {
                __half2 h0 = __floats2half2_rn(acc[i][0], acc[i][1]);
                __half2 h1 = __floats2half2_rn(acc[i][2], acc[i][3]);
                __half2* o2 = (__half2*)((__half*)out + (size_t)gr * 64 + c0);
                o2[0] = h0; o2[1] = h1;
            } else {
                *(float4*)&((float*)out)[(size_t)gr * NC + c0] =
                    make_float4(acc[i][0], acc[i][1], acc[i][2], acc[i][3]);
            }
        }
    }
}

// ---------------- aggregation (NC=64, fp16 h): quarter-warp uint4, 4 edges/iter ----------
__global__ void k_agg64h(const uint4* __restrict__ h4, const float* __restrict__ bias,
                         const float* __restrict__ t, float* __restrict__ out) {
    int wid  = (blockIdx.x * blockDim.x + threadIdx.x) >> 5;
    int lane = threadIdx.x & 31;
    if (wid >= NN) return;
    int q = lane >> 3, ql = lane & 7;
    int st = g_start[wid], en = st + g_deg[wid];
    float acc[8];
    #pragma unroll
    for (int i = 0; i < 8; i++) acc[i] = 0.f;

    #pragma unroll 2
    for (int e = st + q; e < en; e += 4) {
        int2 c = __ldg(&g_cw[e]);
        uint4 v = __ldg(h4 + (size_t)c.x * 8 + ql);   // 8 halves of the row
        float w = __int_as_float(c.y);
        float2 f;
        f = __half22float2(*(const __half2*)&v.x); acc[0] += w * f.x; acc[1] += w * f.y;
        f = __half22float2(*(const __half2*)&v.y); acc[2] += w * f.x; acc[3] += w * f.y;
        f = __half22float2(*(const __half2*)&v.z); acc[4] += w * f.x; acc[5] += w * f.y;
        f = __half22float2(*(const __half2*)&v.w); acc[6] += w * f.x; acc[7] += w * f.y;
    }
    #pragma unroll
    for (int i = 0; i < 8; i++) {
        acc[i] += __shfl_xor_sync(0xffffffffu, acc[i], 8);
        acc[i] += __shfl_xor_sync(0xffffffffu, acc[i], 16);
    }
    if (q == 0) {   // lanes 0-7 hold full sums for cols ql*8 .. ql*8+7
        float sd = g_s[wid];
        const float4* b4 = (const float4*)(bias + ql * 8);
        const float4* t4 = (const float4*)(t + ql * 8);
        float4 b0 = __ldg(b4), b1 = __ldg(b4 + 1);
        float4 t0 = __ldg(t4), t1 = __ldg(t4 + 1);
        float4 o0, o1;
        o0.x = acc[0] + b0.x + sd * t0.x;
        o0.y = acc[1] + b0.y + sd * t0.y;
        o0.z = acc[2] + b0.z + sd * t0.z;
        o0.w = acc[3] + b0.w + sd * t0.w;
        o1.x = acc[4] + b1.x + sd * t1.x;
        o1.y = acc[5] + b1.y + sd * t1.y;
        o1.z = acc[6] + b1.z + sd * t1.z;
        o1.w = acc[7] + b1.w + sd * t1.w;
        float4* op = (float4*)(out + (size_t)wid * 64 + ql * 8);
        op[0] = o0; op[1] = o1;
    }
}

// ---------------- aggregation (NC=40, fp32 h) + fused log_softmax ----------------
// Half-warp float4: 40 floats = 10 lanes x float4 per edge; warp covers 2 edges
// per iteration (half 0 even CSR slots, half 1 odd), combined by shfl_down(16).
__global__ void k_agg40lsm(const float4* __restrict__ h4, const float* __restrict__ bias,
                           const float* __restrict__ t, float* __restrict__ emb,
                           float* __restrict__ out) {
    int wid  = (blockIdx.x * blockDim.x + threadIdx.x) >> 5;
    int lane = threadIdx.x & 31;
    if (wid >= NN) return;
    int half = lane >> 4, hl = lane & 15;
    bool act = hl < 10;
    int st = g_start[wid], deg = g_deg[wid];
    int pairs = deg >> 1;
    int base = st + half;
    float ax = 0.f, ay = 0.f, az = 0.f, aw = 0.f;
    int i = 0;
    while (i + 2 <= pairs) {
        int2 ca = __ldg(&g_cw[base + 2 * i]);
        int2 cb = __ldg(&g_cw[base + 2 * i + 2]);
        if (act) {
            float4 va = __ldg(h4 + (size_t)ca.x * 10 + hl);
            float4 vb = __ldg(h4 + (size_t)cb.x * 10 + hl);
            float wa = __int_as_float(ca.y), wb = __int_as_float(cb.y);
            ax += wa * va.x; ay += wa * va.y; az += wa * va.z; aw += wa * va.w;
            ax += wb * vb.x; ay += wb * vb.y; az += wb * vb.z; aw += wb * vb.w;
        }
        i += 2;
    }
    if (i < pairs) {
        int2 c = __ldg(&g_cw[base + 2 * i]);
        if (act) {
            float4 v = __ldg(h4 + (size_t)c.x * 10 + hl);
            float w = __int_as_float(c.y);
            ax += w * v.x; ay += w * v.y; az += w * v.z; aw += w * v.w;
        }
    }
    if ((deg & 1) && half == 0) {          // odd tail edge handled by half 0
        int2 c = __ldg(&g_cw[st + deg - 1]);
        if (act) {
            float4 v = __ldg(h4 + (size_t)c.x * 10 + hl);
            float w = __int_as_float(c.y);
            ax += w * v.x; ay += w * v.y; az += w * v.z; aw += w * v.w;
        }
    }
    // combine halves (all 32 lanes execute)
    ax += __shfl_down_sync(0xffffffffu, ax, 16);
    ay += __shfl_down_sync(0xffffffffu, ay, 16);
    az += __shfl_down_sync(0xffffffffu, az, 16);
    aw += __shfl_down_sync(0xffffffffu, aw, 16);

    bool fin = (half == 0) && act;         // lanes 0-9 hold cols hl*4..hl*4+3
    float4 v = make_float4(0.f, 0.f, 0.f, 0.f);
    if (fin) {
        float sd = g_s[wid];
        float4 b4 = __ldg((const float4*)bias + hl);
        float4 t4 = __ldg((const float4*)t + hl);
        v.x = ax + b4.x + sd * t4.x;
        v.y = ay + b4.y + sd * t4.y;
        v.z = az + b4.z + sd * t4.z;
        v.w = aw + b4.w + sd * t4.w;
        ((float4*)emb)[(size_t)wid * 10 + hl] = v;
    }
    float m = fin ? fmaxf(fmaxf(v.x, v.y), fmaxf(v.z, v.w)) : -3.4e38f;
    #pragma unroll
    for (int o = 16; o > 0; o >>= 1) m = fmaxf(m, __shfl_xor_sync(0xffffffffu, m, o));
    float s = fin ? (__expf(v.x - m) + __expf(v.y - m) + __expf(v.z - m) + __expf(v.w - m)) : 0.f;
    #pragma unroll
    for (int o = 16; o > 0; o >>= 1) s += __shfl_xor_sync(0xffffffffu, s, o);
    float lse = m + logf(s);
    if (fin)
        ((float4*)out)[(size_t)wid * 10 + hl] =
            make_float4(v.x - lse, v.y - lse, v.z - lse, v.w - lse);
}

// ---------------- BN column stats (sum, sumsq) ----------------
__global__ void k_stats(const float* __restrict__ a, float* __restrict__ st) {
    int col = threadIdx.x & 63, sub = threadIdx.x >> 6;
    float s = 0.f, q = 0.f;
    for (int r = blockIdx.x * 4 + sub; r < NN; r += gridDim.x * 4) {
        float v = a[(size_t)r * 64 + col];
        s += v; q += v * v;
    }
    __shared__ float shs[256], shq[256];
    shs[threadIdx.x] = s; shq[threadIdx.x] = q;
    __syncthreads();
    if (sub == 0) {
        s = shs[col] + shs[col + 64] + shs[col + 128] + shs[col + 192];
        q = shq[col] + shq[col + 64] + shq[col + 128] + shq[col + 192];
        atomicAdd(&st[col], s);
        atomicAdd(&st[col + 64], q);
    }
}

// ---------------- fold BN into next layer's weights ----------------
template <int NCN>
__global__ void k_fold(const float* __restrict__ W, const float* __restrict__ g,
                       const float* __restrict__ be, const float* __restrict__ st,
                       float* __restrict__ Wf, float* __restrict__ t) {
    __shared__ float a[64], c[64];
    int tid = threadIdx.x;
    if (tid < 64) {
        float mean = st[tid] * (1.f / NN);
        float var  = st[tid + 64] * (1.f / NN) - mean * mean;
        float ai = g[tid] * rsqrtf(var + EPSV);
        a[tid] = ai;
        c[tid] = be[tid] - mean * ai;
    }
    __syncthreads();
    for (int i = tid; i < 64 * NCN; i += 256) Wf[i] = a[i / NCN] * W[i];
    if (tid < NCN) {
        float tv = 0.f;
        #pragma unroll
        for (int k = 0; k < 64; k++) tv += c[k] * W[k * NCN + tid];
        t[tid] = tv;
    }
}

// ---------------- launcher ----------------
extern "C" void kernel_launch(void* const* d_in, const int* in_sizes, int n_in,
                              void* d_out, int out_size) {
    const float* x   = (const float*)d_in[0];
    const void*  ei  = d_in[1];                 // int32 or int64, detected on device
    const float* W1  = (const float*)d_in[2];
    const float* b1  = (const float*)d_in[3];
    const float* W2  = (const float*)d_in[4];
    const float* b2  = (const float*)d_in[5];
    const float* W3  = (const float*)d_in[6];
    const float* b3  = (const float*)d_in[7];
    const float* g1  = (const float*)d_in[8];
    const float* be1 = (const float*)d_in[9];
    const float* g2  = (const float*)d_in[10];
    const float* be2 = (const float*)d_in[11];
    float* out = (float*)d_out;

    float *hP, *aP, *W2fP, *W3fP, *t2P, *t3P, *z64P, *s1P, *s2P;
    cudaGetSymbolAddress((void**)&hP,   g_h);
    cudaGetSymbolAddress((void**)&aP,   g_agg);
    cudaGetSymbolAddress((void**)&W2fP, g_W2f);
    cudaGetSymbolAddress((void**)&W3fP, g_W3f);
    cudaGetSymbolAddress((void**)&t2P,  g_t2);
    cudaGetSymbolAddress((void**)&t3P,  g_t3);
    cudaGetSymbolAddress((void**)&z64P, g_zero64);
    cudaGetSymbolAddress((void**)&s1P,  g_stats1);
    cudaGetSymbolAddress((void**)&s2P,  g_stats2);

    // output layout: (out, emb) concatenated
    float* emb = (out_size >= 2 * NN * 40) ? (out + NN * 40) : aP;

    // graph build (single stream; R7 showed forked capture regresses)
    k_init  <<<(NN + 255) / 256, 256>>>((const long long*)ei);
    k_degree<<<(EE + 255) / 256, 256>>>(ei);
    k_scanA <<<NB, 256>>>();
    k_scanC <<<NB, 256>>>();
    k_fill  <<<(MM + 255) / 256, 256>>>(ei);

    // layer 1 (h in fp16)
    k_gemm<64, true><<<(NN + 63) / 64, 256>>>(x, W1, hP);
    k_agg64h  <<<(NN + 7) / 8, 256>>>((const uint4*)hP, b1, z64P, aP);
    k_stats   <<<256, 256>>>(aP, s1P);
    k_fold<64><<<1, 256>>>(W2, g1, be1, s1P, W2fP, t2P);

    // layer 2 (BN1 folded into W2, h in fp16)
    k_gemm<64, true><<<(NN + 63) / 64, 256>>>(aP, W2fP, hP);
    k_agg64h  <<<(NN + 7) / 8, 256>>>((const uint4*)hP, b2, t2P, aP);
    k_stats   <<<256, 256>>>(aP, s2P);
    k_fold<40><<<1, 256>>>(W3, g2, be2, s2P, W3fP, t3P);

    // layer 3 (BN2 folded into W3, fp32 throughout) -> emb + fused log_softmax -> out
    k_gemm<40, false><<<(NN + 63) / 64, 160>>>(aP, W3fP, hP);
    k_agg40lsm<<<(NN + 7) / 8, 256>>>((const float4*)hP, b3, t3P, emb, out);
}

// round 11
// speedup vs baseline: 1.3375x; 1.1037x over previous
#include <cuda_runtime.h>
#include <cuda_fp16.h>
#include <math.h>

#define NN 100000
#define EE 1600000
#define MM (EE + NN)
#define NB 49            // ceil(NN / 2048)
#define EPSV 1e-5f

// ---------------- scratch (static device allocations; no cudaMalloc) ----------------
__device__ int   g_is64 = 1;        // detection only ever clears -> stable across replays
__device__ int   g_deg[NN];
__device__ float g_dinv[NN];
__device__ int   g_start[NN];
__device__ int   g_cursor[NN];
__device__ int   g_tilesum[NB];
__device__ int2  g_cw[MM];          // (src, norm-bits) per CSR slot
__device__ float g_s[NN];           // row sums of normalized adjacency
__device__ __align__(16) float g_h[NN * 64];      // GEMM out: fp16 (L1/2) or fp32 (L3)
__device__ __align__(16) float g_agg[NN * 64];    // aggregation output (fp32)
__device__ float g_stats1[32 * 128];  // 32 contention buckets x [sum(64), sumsq(64)]
__device__ float g_stats2[32 * 128];
__device__ float g_W2f[64 * 64];    // BN1-folded W2
__device__ __align__(16) float g_W3f[64 * 40];    // BN2-folded W3
__device__ float g_t2[64];
__device__ __align__(16) float g_t3[64];
__device__ __align__(16) float g_zero64[64];

// ---------------- graph init + sampled dtype detect ----------------
__global__ void k_init(const long long* __restrict__ p) {
    int i = blockIdx.x * blockDim.x + threadIdx.x;
    if (i < NN) { g_deg[i] = 1; g_s[i] = 0.f; }      // self-loop
    if (i < 32 * 128) { g_stats1[i] = 0.f; g_stats2[i] = 0.f; }
    if (i < 64) g_zero64[i] = 0.f;
    if (i < 8192) {
        long long v = p[(size_t)i * 195];            // max idx < EE int64 slots
        if (v < 0 || v >= NN) g_is64 = 0;            // only writes 0: race-free
    }
}

// ---------------- degree: 4 edges per thread ----------------
__global__ void k_degree(const void* __restrict__ ei) {
    int i = blockIdx.x * blockDim.x + threadIdx.x;
    if (i >= EE / 4) return;
    if (g_is64) {
        const longlong2* p = (const longlong2*)ei;
        longlong2 a = p[EE / 2 + i * 2];
        longlong2 b = p[EE / 2 + i * 2 + 1];
        if ((unsigned long long)a.x < NN) atomicAdd(&g_deg[(int)a.x], 1);
        if ((unsigned long long)a.y < NN) atomicAdd(&g_deg[(int)a.y], 1);
        if ((unsigned long long)b.x < NN) atomicAdd(&g_deg[(int)b.x], 1);
        if ((unsigned long long)b.y < NN) atomicAdd(&g_deg[(int)b.y], 1);
    } else {
        int4 v = ((const int4*)ei)[EE / 4 + i];
        if ((unsigned)v.x < NN) atomicAdd(&g_deg[v.x], 1);
        if ((unsigned)v.y < NN) atomicAdd(&g_deg[v.y], 1);
        if ((unsigned)v.z < NN) atomicAdd(&g_deg[v.z], 1);
        if ((unsigned)v.w < NN) atomicAdd(&g_deg[v.w], 1);
    }
}

__global__ void k_scanA() {   // block-tile sums (tile = 2048) + fused dinv
    int base = blockIdx.x * 2048;
    int s = 0;
    for (int i = threadIdx.x; i < 2048; i += 256) {
        int idx = base + i;
        if (idx < NN) {
            int d = g_deg[idx];
            s += d;
            g_dinv[idx] = rsqrtf((float)d);
        }
    }
    __shared__ int sh[256];
    sh[threadIdx.x] = s;
    __syncthreads();
    for (int o = 128; o > 0; o >>= 1) {
        if (threadIdx.x < o) sh[threadIdx.x] += sh[threadIdx.x + o];
        __syncthreads();
    }
    if (threadIdx.x == 0) g_tilesum[blockIdx.x] = sh[0];
}

// intra-tile exclusive scan -> start/cursor; tile offset computed in-kernel
__global__ void k_scanC() {
    int tid = threadIdx.x;
    __shared__ int s_off;
    if (tid < 32) {
        int v = 0;
        for (int j = tid; j < blockIdx.x; j += 32) v += g_tilesum[j];
        #pragma unroll
        for (int o = 16; o > 0; o >>= 1) v += __shfl_xor_sync(0xffffffffu, v, o);
        if (tid == 0) s_off = v;
    }
    int base = blockIdx.x * 2048 + tid * 8;
    int loc[8];
    int s = 0;
    #pragma unroll
    for (int j = 0; j < 8; j++) {
        int idx = base + j;
        int d = (idx < NN) ? g_deg[idx] : 0;
        loc[j] = s; s += d;
    }
    __shared__ int sh[256];
    sh[tid] = s;
    __syncthreads();
    int run = s;
    for (int o = 1; o < 256; o <<= 1) {
        int v = (tid >= o) ? sh[tid - o] : 0;
        __syncthreads();
        sh[tid] += v;
        __syncthreads();
    }
    int off = s_off + sh[tid] - run;
    #pragma unroll
    for (int j = 0; j < 8; j++) {
        int idx = base + j;
        if (idx < NN) { int p = off + loc[j]; g_start[idx] = p; g_cursor[idx] = p; }
    }
}

// CSR fill + fused row-sum; 4 edges per thread, self-loops appended.
__device__ __forceinline__ void fill_one(int s, int d) {
    float w = g_dinv[s] * g_dinv[d];
    int pos = atomicAdd(&g_cursor[d], 1);
    g_cw[pos] = make_int2(s, __float_as_int(w));
    atomicAdd(&g_s[d], w);
}

__global__ void k_fill(const void* __restrict__ ei) {
    int i = blockIdx.x * blockDim.x + threadIdx.x;
    if (i < EE / 4) {
        if (g_is64) {
            const longlong2* p = (const longlong2*)ei;
            longlong2 sa = p[i * 2],           sb = p[i * 2 + 1];
            longlong2 da = p[EE / 2 + i * 2],  db = p[EE / 2 + i * 2 + 1];
            if ((unsigned long long)sa.x < NN && (unsigned long long)da.x < NN)
                fill_one((int)sa.x, (int)da.x);
            if ((unsigned long long)sa.y < NN && (unsigned long long)da.y < NN)
                fill_one((int)sa.y, (int)da.y);
            if ((unsigned long long)sb.x < NN && (unsigned long long)db.x < NN)
                fill_one((int)sb.x, (int)db.x);
            if ((unsigned long long)sb.y < NN && (unsigned long long)db.y < NN)
                fill_one((int)sb.y, (int)db.y);
        } else {
            int4 sv = ((const int4*)ei)[i];
            int4 dv = ((const int4*)ei)[EE / 4 + i];
            if ((unsigned)sv.x < NN && (unsigned)dv.x < NN) fill_one(sv.x, dv.x);
            if ((unsigned)sv.y < NN && (unsigned)dv.y < NN) fill_one(sv.y, dv.y);
            if ((unsigned)sv.z < NN && (unsigned)dv.z < NN) fill_one(sv.z, dv.z);
            if ((unsigned)sv.w < NN && (unsigned)dv.w < NN) fill_one(sv.w, dv.w);
        }
    } else {
        int n = i - EE / 4;
        if (n < NN) fill_one(n, n);        // self-loop
    }
}

// ---------------- GEMM: out[N x NC] = in[N x 64] @ W[64 x NC] ----------------
// fp32 compute; output fp16 (HOUT, row stride 64 halves) or fp32.
// blockDim must be (NC/4)*16; block tile = 64 rows x NC cols.
template <int NC, bool HOUT>
__global__ void k_gemm(const float* __restrict__ in, const float* __restrict__ W,
                       void* __restrict__ out) {
    __shared__ float XsT[64 * 68];   // [k][row], padded
    __shared__ float Ws[64 * NC];    // [k][j]
    const int nth = (NC / 4) * 16;
    int tid = threadIdx.x;
    int row0 = blockIdx.x * 64;

    for (int i = tid; i < 64 * NC / 4; i += nth)
        ((float4*)Ws)[i] = ((const float4*)W)[i];

    for (int i = tid; i < 64 * 16; i += nth) {
        int r = i & 63, k4 = i >> 6;
        int gr = row0 + r;
        float4 v = make_float4(0.f, 0.f, 0.f, 0.f);
        if (gr < NN) v = ((const float4*)(in + (size_t)gr * 64))[k4];
        XsT[(k4 * 4 + 0) * 68 + r] = v.x;
        XsT[(k4 * 4 + 1) * 68 + r] = v.y;
        XsT[(k4 * 4 + 2) * 68 + r] = v.z;
        XsT[(k4 * 4 + 3) * 68 + r] = v.w;
    }
    __syncthreads();

    int tc = tid % (NC / 4), tr = tid / (NC / 4);
    int c0 = tc * 4, r0 = tr * 4;
    float acc[4][4];
    #pragma unroll
    for (int i = 0; i < 4; i++)
        #pragma unroll
        for (int j = 0; j < 4; j++) acc[i][j] = 0.f;

    #pragma unroll 8
    for (int k = 0; k < 64; k++) {
        float4 b = *(const float4*)&Ws[k * NC + c0];
        float4 a = *(const float4*)&XsT[k * 68 + r0];
        acc[0][0] += a.x * b.x; acc[0][1] += a.x * b.y; acc[0][2] += a.x * b.z; acc[0][3] += a.x * b.w;
        acc[1][0] += a.y * b.x; acc[1][1] += a.y * b.y; acc[1][2] += a.y * b.z; acc[1][3] += a.y * b.w;
        acc[2][0] += a.z * b.x; acc[2][1] += a.z * b.y; acc[2][2] += a.z * b.z; acc[2][3] += a.z * b.w;
        acc[3][0] += a.w * b.x; acc[3][1] += a.w * b.y; acc[3][2] += a.w * b.z; acc[3][3] += a.w * b.w;
    }

    #pragma unroll
    for (int i = 0; i < 4; i++) {
        int gr = row0 + r0 + i;
        if (gr < NN) {
            if (HOUT) {
                __half2 h0 = __floats2half2_rn(acc[i][0], acc[i][1]);
                __half2 h1 = __floats2half2_rn(acc[i][2], acc[i][3]);
                __half2* o2 = (__half2*)((__half*)out + (size_t)gr * 64 + c0);
                o2[0] = h0; o2[1] = h1;
            } else {
                *(float4*)&((float*)out)[(size_t)gr * NC + c0] =
                    make_float4(acc[i][0], acc[i][1], acc[i][2], acc[i][3]);
            }
        }
    }
}

// ---------------- aggregation (NC=64, fp16 h) + fused BN stats ----------------
// Quarter-warp uint4 gather (one warp LDG.128 = 4 edges). Grid is exactly
// 12500 x 8 warps = NN nodes -> no early returns -> __syncthreads is safe.
// Stats: non-atomic per-warp shared stores, tree reduce, flush to 1 of 32
// contention-spreading buckets (~390 atomics/address total).
__global__ void __launch_bounds__(256)
k_agg64h(const uint4* __restrict__ h4, const float* __restrict__ bias,
         const float* __restrict__ t, float* __restrict__ out,
         float* __restrict__ st) {
    __shared__ float s_sum[8][64];
    __shared__ float s_sq[8][64];
    int tid = threadIdx.x;
    int wIdx = tid >> 5;
    int wid  = blockIdx.x * 8 + wIdx;      // always < NN
    int lane = tid & 31;
    int q = lane >> 3, ql = lane & 7;
    int stt = g_start[wid], en = stt + g_deg[wid];
    float acc[8];
    #pragma unroll
    for (int i = 0; i < 8; i++) acc[i] = 0.f;

    #pragma unroll 2
    for (int e = stt + q; e < en; e += 4) {
        int2 c = __ldg(&g_cw[e]);
        uint4 v = __ldg(h4 + (size_t)c.x * 8 + ql);   // 8 halves of the row
        float w = __int_as_float(c.y);
        float2 f;
        f = __half22float2(*(const __half2*)&v.x); acc[0] += w * f.x; acc[1] += w * f.y;
        f = __half22float2(*(const __half2*)&v.y); acc[2] += w * f.x; acc[3] += w * f.y;
        f = __half22float2(*(const __half2*)&v.z); acc[4] += w * f.x; acc[5] += w * f.y;
        f = __half22float2(*(const __half2*)&v.w); acc[6] += w * f.x; acc[7] += w * f.y;
    }
    #pragma unroll
    for (int i = 0; i < 8; i++) {
        acc[i] += __shfl_xor_sync(0xffffffffu, acc[i], 8);
        acc[i] += __shfl_xor_sync(0xffffffffu, acc[i], 16);
    }
    if (q == 0) {   // lanes 0-7 hold full sums for cols ql*8 .. ql*8+7
        float sd = g_s[wid];
        const float4* b4 = (const float4*)(bias + ql * 8);
        const float4* t4 = (const float4*)(t + ql * 8);
        float4 b0 = __ldg(b4), b1 = __ldg(b4 + 1);
        float4 t0 = __ldg(t4), t1 = __ldg(t4 + 1);
        float o[8];
        o[0] = acc[0] + b0.x + sd * t0.x;
        o[1] = acc[1] + b0.y + sd * t0.y;
        o[2] = acc[2] + b0.z + sd * t0.z;
        o[3] = acc[3] + b0.w + sd * t0.w;
        o[4] = acc[4] + b1.x + sd * t1.x;
        o[5] = acc[5] + b1.y + sd * t1.y;
        o[6] = acc[6] + b1.z + sd * t1.z;
        o[7] = acc[7] + b1.w + sd * t1.w;
        float4* op = (float4*)(out + (size_t)wid * 64 + ql * 8);
        op[0] = make_float4(o[0], o[1], o[2], o[3]);
        op[1] = make_float4(o[4], o[5], o[6], o[7]);
        #pragma unroll
        for (int i = 0; i < 8; i++) {
            s_sum[wIdx][ql * 8 + i] = o[i];
            s_sq [wIdx][ql * 8 + i] = o[i] * o[i];
        }
    }
    __syncthreads();
    if (tid < 64) {
        float a = 0.f, b = 0.f;
        #pragma unroll
        for (int w = 0; w < 8; w++) { a += s_sum[w][tid]; b += s_sq[w][tid]; }
        int bkt = (blockIdx.x & 31) * 128;
        atomicAdd(&st[bkt + tid], a);
        atomicAdd(&st[bkt + tid + 64], b);
    }
}

// ---------------- aggregation (NC=40, fp32 h) + fused log_softmax ----------------
// Half-warp float4: 40 floats = 10 lanes x float4 per edge; 2 edges/warp/iter.
__global__ void k_agg40lsm(const float4* __restrict__ h4, const float* __restrict__ bias,
                           const float* __restrict__ t, float* __restrict__ emb,
                           float* __restrict__ out) {
    int wid  = (blockIdx.x * blockDim.x + threadIdx.x) >> 5;
    int lane = threadIdx.x & 31;
    if (wid >= NN) return;
    int half = lane >> 4, hl = lane & 15;
    bool act = hl < 10;
    int st = g_start[wid], deg = g_deg[wid];
    int pairs = deg >> 1;
    int base = st + half;
    float ax = 0.f, ay = 0.f, az = 0.f, aw = 0.f;
    int i = 0;
    while (i + 2 <= pairs) {
        int2 ca = __ldg(&g_cw[base + 2 * i]);
        int2 cb = __ldg(&g_cw[base + 2 * i + 2]);
        if (act) {
            float4 va = __ldg(h4 + (size_t)ca.x * 10 + hl);
            float4 vb = __ldg(h4 + (size_t)cb.x * 10 + hl);
            float wa = __int_as_float(ca.y), wb = __int_as_float(cb.y);
            ax += wa * va.x; ay += wa * va.y; az += wa * va.z; aw += wa * va.w;
            ax += wb * vb.x; ay += wb * vb.y; az += wb * vb.z; aw += wb * vb.w;
        }
        i += 2;
    }
    if (i < pairs) {
        int2 c = __ldg(&g_cw[base + 2 * i]);
        if (act) {
            float4 v = __ldg(h4 + (size_t)c.x * 10 + hl);
            float w = __int_as_float(c.y);
            ax += w * v.x; ay += w * v.y; az += w * v.z; aw += w * v.w;
        }
    }
    if ((deg & 1) && half == 0) {          // odd tail edge handled by half 0
        int2 c = __ldg(&g_cw[st + deg - 1]);
        if (act) {
            float4 v = __ldg(h4 + (size_t)c.x * 10 + hl);
            float w = __int_as_float(c.y);
            ax += w * v.x; ay += w * v.y; az += w * v.z; aw += w * v.w;
        }
    }
    ax += __shfl_down_sync(0xffffffffu, ax, 16);
    ay += __shfl_down_sync(0xffffffffu, ay, 16);
    az += __shfl_down_sync(0xffffffffu, az, 16);
    aw += __shfl_down_sync(0xffffffffu, aw, 16);

    bool fin = (half == 0) && act;         // lanes 0-9 hold cols hl*4..hl*4+3
    float4 v = make_float4(0.f, 0.f, 0.f, 0.f);
    if (fin) {
        float sd = g_s[wid];
        float4 b4 = __ldg((const float4*)bias + hl);
        float4 t4 = __ldg((const float4*)t + hl);
        v.x = ax + b4.x + sd * t4.x;
        v.y = ay + b4.y + sd * t4.y;
        v.z = az + b4.z + sd * t4.z;
        v.w = aw + b4.w + sd * t4.w;
        ((float4*)emb)[(size_t)wid * 10 + hl] = v;
    }
    float m = fin ? fmaxf(fmaxf(v.x, v.y), fmaxf(v.z, v.w)) : -3.4e38f;
    #pragma unroll
    for (int o = 16; o > 0; o >>= 1) m = fmaxf(m, __shfl_xor_sync(0xffffffffu, m, o));
    float s = fin ? (__expf(v.x - m) + __expf(v.y - m) + __expf(v.z - m) + __expf(v.w - m)) : 0.f;
    #pragma unroll
    for (int o = 16; o > 0; o >>= 1) s += __shfl_xor_sync(0xffffffffu, s, o);
    float lse = m + logf(s);
    if (fin)
        ((float4*)out)[(size_t)wid * 10 + hl] =
            make_float4(v.x - lse, v.y - lse, v.z - lse, v.w - lse);
}

// ---------------- fold BN into next layer's weights (reads 32 stat buckets) ----------
template <int NCN>
__global__ void k_fold(const float* __restrict__ W, const float* __restrict__ g,
                       const float* __restrict__ be, const float* __restrict__ st,
                       float* __restrict__ Wf, float* __restrict__ t) {
    __shared__ float a[64], c[64];
    int tid = threadIdx.x;
    __shared__ float red[128];
    if (tid < 128) {
        float v = 0.f;
        #pragma unroll 8
        for (int b = 0; b < 32; b++) v += st[b * 128 + tid];
        red[tid] = v;
    }
    __syncthreads();
    if (tid < 64) {
        float mean = red[tid] * (1.f / NN);
        float var  = red[tid + 64] * (1.f / NN) - mean * mean;
        float ai = g[tid] * rsqrtf(var + EPSV);
        a[tid] = ai;
        c[tid] = be[tid] - mean * ai;
    }
    __syncthreads();
    for (int i = tid; i < 64 * NCN; i += 256) Wf[i] = a[i / NCN] * W[i];
    if (tid < NCN) {
        float tv = 0.f;
        #pragma unroll
        for (int k = 0; k < 64; k++) tv += c[k] * W[k * NCN + tid];
        t[tid] = tv;
    }
}

// ---------------- launcher ----------------
extern "C" void kernel_launch(void* const* d_in, const int* in_sizes, int n_in,
                              void* d_out, int out_size) {
    const float* x   = (const float*)d_in[0];
    const void*  ei  = d_in[1];                 // int32 or int64, detected on device
    const float* W1  = (const float*)d_in[2];
    const float* b1  = (const float*)d_in[3];
    const float* W2  = (const float*)d_in[4];
    const float* b2  = (const float*)d_in[5];
    const float* W3  = (const float*)d_in[6];
    const float* b3  = (const float*)d_in[7];
    const float* g1  = (const float*)d_in[8];
    const float* be1 = (const float*)d_in[9];
    const float* g2  = (const float*)d_in[10];
    const float* be2 = (const float*)d_in[11];
    float* out = (float*)d_out;

    float *hP, *aP, *W2fP, *W3fP, *t2P, *t3P, *z64P, *s1P, *s2P;
    cudaGetSymbolAddress((void**)&hP,   g_h);
    cudaGetSymbolAddress((void**)&aP,   g_agg);
    cudaGetSymbolAddress((void**)&W2fP, g_W2f);
    cudaGetSymbolAddress((void**)&W3fP, g_W3f);
    cudaGetSymbolAddress((void**)&t2P,  g_t2);
    cudaGetSymbolAddress((void**)&t3P,  g_t3);
    cudaGetSymbolAddress((void**)&z64P, g_zero64);
    cudaGetSymbolAddress((void**)&s1P,  g_stats1);
    cudaGetSymbolAddress((void**)&s2P,  g_stats2);

    // output layout: (out, emb) concatenated
    float* emb = (out_size >= 2 * NN * 40) ? (out + NN * 40) : aP;

    // graph build (single stream; R7 showed forked capture regresses)
    k_init  <<<(NN + 255) / 256, 256>>>((const long long*)ei);
    k_degree<<<(EE / 4 + 255) / 256, 256>>>(ei);
    k_scanA <<<NB, 256>>>();
    k_scanC <<<NB, 256>>>();
    k_fill  <<<(EE / 4 + NN + 255) / 256, 256>>>(ei);

    // layer 1 (h in fp16, stats fused into agg)
    k_gemm<64, true><<<(NN + 63) / 64, 256>>>(x, W1, hP);
    k_agg64h  <<<NN / 8, 256>>>((const uint4*)hP, b1, z64P, aP, s1P);
    k_fold<64><<<1, 256>>>(W2, g1, be1, s1P, W2fP, t2P);

    // layer 2 (BN1 folded into W2, h in fp16, stats fused)
    k_gemm<64, true><<<(NN + 63) / 64, 256>>>(aP, W2fP, hP);
    k_agg64h  <<<NN / 8, 256>>>((const uint4*)hP, b2, t2P, aP, s2P);
    k_fold<40><<<1, 256>>>(W3, g2, be2, s2P, W3fP, t3P);

    // layer 3 (BN2 folded into W3, fp32 throughout) -> emb + fused log_softmax -> out
    k_gemm<40, false><<<(NN + 63) / 64, 160>>>(aP, W3fP, hP);
    k_agg40lsm<<<(NN + 7) / 8, 256>>>((const float4*)hP, b3, t3P, emb, out);
}

// round 12
// speedup vs baseline: 1.4294x; 1.0687x over previous
#include <cuda_runtime.h>
#include <cuda_fp16.h>
#include <math.h>

#define NN 100000
#define EE 1600000
#define MM (EE + NN)
#define NT 391           // ceil(NN / 256) scan tiles
#define EPSV 1e-5f

// ---------------- scratch (static device allocations; no cudaMalloc) ----------------
__device__ int   g_is64 = 1;        // detection only ever clears -> stable across replays
__device__ int   g_deg[NN];
__device__ float g_dinv[NN];
__device__ int   g_start[NN];
__device__ int   g_cursor[NN];
__device__ int   g_tilesum[NT];
__device__ int2  g_cw[MM];          // (src, norm-bits) per CSR slot
__device__ __align__(16) float g_h[NN * 64];      // GEMM out: fp16 (L1/2) or fp32 (L3)
__device__ __align__(16) float g_agg[NN * 64];    // aggregation output (fp32)
__device__ float g_stats1[32 * 128];  // 32 contention buckets x [sum(64), sumsq(64)]
__device__ float g_stats2[32 * 128];
__device__ float g_W2f[64 * 64];    // BN1-folded W2
__device__ __align__(16) float g_W3f[64 * 40];    // BN2-folded W3
__device__ float g_t2[64];
__device__ __align__(16) float g_t3[64];
__device__ __align__(16) float g_zero64[64];

// ---------------- graph init + sampled dtype detect ----------------
__global__ void k_init(const long long* __restrict__ p) {
    int i = blockIdx.x * blockDim.x + threadIdx.x;
    if (i < NN) g_deg[i] = 1;                        // self-loop
    if (i < 32 * 128) { g_stats1[i] = 0.f; g_stats2[i] = 0.f; }
    if (i < 64) g_zero64[i] = 0.f;
    if (i < 8192) {
        long long v = p[(size_t)i * 195];            // max idx < EE int64 slots
        if (v < 0 || v >= NN) g_is64 = 0;            // only writes 0: race-free
    }
}

// ---------------- degree: 4 edges per thread ----------------
__global__ void k_degree(const void* __restrict__ ei) {
    int i = blockIdx.x * blockDim.x + threadIdx.x;
    if (i >= EE / 4) return;
    if (g_is64) {
        const longlong2* p = (const longlong2*)ei;
        longlong2 a = p[EE / 2 + i * 2];
        longlong2 b = p[EE / 2 + i * 2 + 1];
        if ((unsigned long long)a.x < NN) atomicAdd(&g_deg[(int)a.x], 1);
        if ((unsigned long long)a.y < NN) atomicAdd(&g_deg[(int)a.y], 1);
        if ((unsigned long long)b.x < NN) atomicAdd(&g_deg[(int)b.x], 1);
        if ((unsigned long long)b.y < NN) atomicAdd(&g_deg[(int)b.y], 1);
    } else {
        int4 v = ((const int4*)ei)[EE / 4 + i];
        if ((unsigned)v.x < NN) atomicAdd(&g_deg[v.x], 1);
        if ((unsigned)v.y < NN) atomicAdd(&g_deg[v.y], 1);
        if ((unsigned)v.z < NN) atomicAdd(&g_deg[v.z], 1);
        if ((unsigned)v.w < NN) atomicAdd(&g_deg[v.w], 1);
    }
}

// ---------------- scanA: 391 blocks x 256 thr, 1 node/thread + fused dinv ----------
__global__ void k_scanA() {
    int tid = threadIdx.x;
    int idx = blockIdx.x * 256 + tid;
    int d = 0;
    if (idx < NN) {
        d = g_deg[idx];
        g_dinv[idx] = rsqrtf((float)d);
    }
    __shared__ int sh[256];
    sh[tid] = d;
    __syncthreads();
    for (int o = 128; o > 0; o >>= 1) {
        if (tid < o) sh[tid] += sh[tid + o];
        __syncthreads();
    }
    if (tid == 0) g_tilesum[blockIdx.x] = sh[0];
}

// ---------------- scanC: per-block lookback + 256-wide shared scan ----------------
__global__ void k_scanC() {
    int tid = threadIdx.x;
    __shared__ int s_off;
    if (tid < 32) {
        int v = 0;
        for (int j = tid; j < blockIdx.x; j += 32) v += g_tilesum[j];
        #pragma unroll
        for (int o = 16; o > 0; o >>= 1) v += __shfl_xor_sync(0xffffffffu, v, o);
        if (tid == 0) s_off = v;
    }
    int idx = blockIdx.x * 256 + tid;
    int d = (idx < NN) ? g_deg[idx] : 0;
    __shared__ int sh[256];
    sh[tid] = d;
    __syncthreads();
    for (int o = 1; o < 256; o <<= 1) {
        int v = (tid >= o) ? sh[tid - o] : 0;
        __syncthreads();
        sh[tid] += v;
        __syncthreads();
    }
    if (idx < NN) {
        int p = s_off + sh[tid] - d;     // exclusive
        g_start[idx] = p;
        g_cursor[idx] = p;
    }
}

// CSR fill; 4 edges per thread, self-loops appended. (row-sum now computed in agg)
__device__ __forceinline__ void fill_one(int s, int d) {
    float w = g_dinv[s] * g_dinv[d];
    int pos = atomicAdd(&g_cursor[d], 1);
    g_cw[pos] = make_int2(s, __float_as_int(w));
}

__global__ void k_fill(const void* __restrict__ ei) {
    int i = blockIdx.x * blockDim.x + threadIdx.x;
    if (i < EE / 4) {
        if (g_is64) {
            const longlong2* p = (const longlong2*)ei;
            longlong2 sa = p[i * 2],           sb = p[i * 2 + 1];
            longlong2 da = p[EE / 2 + i * 2],  db = p[EE / 2 + i * 2 + 1];
            if ((unsigned long long)sa.x < NN && (unsigned long long)da.x < NN)
                fill_one((int)sa.x, (int)da.x);
            if ((unsigned long long)sa.y < NN && (unsigned long long)da.y < NN)
                fill_one((int)sa.y, (int)da.y);
            if ((unsigned long long)sb.x < NN && (unsigned long long)db.x < NN)
                fill_one((int)sb.x, (int)db.x);
            if ((unsigned long long)sb.y < NN && (unsigned long long)db.y < NN)
                fill_one((int)sb.y, (int)db.y);
        } else {
            int4 sv = ((const int4*)ei)[i];
            int4 dv = ((const int4*)ei)[EE / 4 + i];
            if ((unsigned)sv.x < NN && (unsigned)dv.x < NN) fill_one(sv.x, dv.x);
            if ((unsigned)sv.y < NN && (unsigned)dv.y < NN) fill_one(sv.y, dv.y);
            if ((unsigned)sv.z < NN && (unsigned)dv.z < NN) fill_one(sv.z, dv.z);
            if ((unsigned)sv.w < NN && (unsigned)dv.w < NN) fill_one(sv.w, dv.w);
        }
    } else {
        int n = i - EE / 4;
        if (n < NN) fill_one(n, n);        // self-loop
    }
}

// ---------------- GEMM: out[N x NC] = in[N x 64] @ W[64 x NC] ----------------
template <int NC, bool HOUT>
__global__ void k_gemm(const float* __restrict__ in, const float* __restrict__ W,
                       void* __restrict__ out) {
    __shared__ float XsT[64 * 68];   // [k][row], padded
    __shared__ float Ws[64 * NC];    // [k][j]
    const int nth = (NC / 4) * 16;
    int tid = threadIdx.x;
    int row0 = blockIdx.x * 64;

    for (int i = tid; i < 64 * NC / 4; i += nth)
        ((float4*)Ws)[i] = ((const float4*)W)[i];

    for (int i = tid; i < 64 * 16; i += nth) {
        int r = i & 63, k4 = i >> 6;
        int gr = row0 + r;
        float4 v = make_float4(0.f, 0.f, 0.f, 0.f);
        if (gr < NN) v = ((const float4*)(in + (size_t)gr * 64))[k4];
        XsT[(k4 * 4 + 0) * 68 + r] = v.x;
        XsT[(k4 * 4 + 1) * 68 + r] = v.y;
        XsT[(k4 * 4 + 2) * 68 + r] = v.z;
        XsT[(k4 * 4 + 3) * 68 + r] = v.w;
    }
    __syncthreads();

    int tc = tid % (NC / 4), tr = tid / (NC / 4);
    int c0 = tc * 4, r0 = tr * 4;
    float acc[4][4];
    #pragma unroll
    for (int i = 0; i < 4; i++)
        #pragma unroll
        for (int j = 0; j < 4; j++) acc[i][j] = 0.f;

    #pragma unroll 8
    for (int k = 0; k < 64; k++) {
        float4 b = *(const float4*)&Ws[k * NC + c0];
        float4 a = *(const float4*)&XsT[k * 68 + r0];
        acc[0][0] += a.x * b.x; acc[0][1] += a.x * b.y; acc[0][2] += a.x * b.z; acc[0][3] += a.x * b.w;
        acc[1][0] += a.y * b.x; acc[1][1] += a.y * b.y; acc[1][2] += a.y * b.z; acc[1][3] += a.y * b.w;
        acc[2][0] += a.z * b.x; acc[2][1] += a.z * b.y; acc[2][2] += a.z * b.z; acc[2][3] += a.z * b.w;
        acc[3][0] += a.w * b.x; acc[3][1] += a.w * b.y; acc[3][2] += a.w * b.z; acc[3][3] += a.w * b.w;
    }

    #pragma unroll
    for (int i = 0; i < 4; i++) {
        int gr = row0 + r0 + i;
        if (gr < NN) {
            if (HOUT) {
                __half2 h0 = __floats2half2_rn(acc[i][0], acc[i][1]);
                __half2 h1 = __floats2half2_rn(acc[i][2], acc[i][3]);
                __half2* o2 = (__half2*)((__half*)out + (size_t)gr * 64 + c0);
                o2[0] = h0; o2[1] = h1;
            } else {
                *(float4*)&((float*)out)[(size_t)gr * NC + c0] =
                    make_float4(acc[i][0], acc[i][1], acc[i][2], acc[i][3]);
            }
        }
    }
}

// ---------------- aggregation (NC=64, fp16 h) + fused BN stats + in-loop row-sum ----
__global__ void __launch_bounds__(256)
k_agg64h(const uint4* __restrict__ h4, const float* __restrict__ bias,
         const float* __restrict__ t, float* __restrict__ out,
         float* __restrict__ st) {
    __shared__ float s_sum[8][64];
    __shared__ float s_sq[8][64];
    int tid = threadIdx.x;
    int wIdx = tid >> 5;
    int wid  = blockIdx.x * 8 + wIdx;      // always < NN
    int lane = tid & 31;
    int q = lane >> 3, ql = lane & 7;
    int stt = g_start[wid], en = stt + g_deg[wid];
    float acc[8];
    float accw = 0.f;                      // row-sum of norms (replaces g_s)
    #pragma unroll
    for (int i = 0; i < 8; i++) acc[i] = 0.f;

    #pragma unroll 2
    for (int e = stt + q; e < en; e += 4) {
        int2 c = __ldg(&g_cw[e]);
        uint4 v = __ldg(h4 + (size_t)c.x * 8 + ql);   // 8 halves of the row
        float w = __int_as_float(c.y);
        accw += w;
        float2 f;
        f = __half22float2(*(const __half2*)&v.x); acc[0] += w * f.x; acc[1] += w * f.y;
        f = __half22float2(*(const __half2*)&v.y); acc[2] += w * f.x; acc[3] += w * f.y;
        f = __half22float2(*(const __half2*)&v.z); acc[4] += w * f.x; acc[5] += w * f.y;
        f = __half22float2(*(const __half2*)&v.w); acc[6] += w * f.x; acc[7] += w * f.y;
    }
    #pragma unroll
    for (int i = 0; i < 8; i++) {
        acc[i] += __shfl_xor_sync(0xffffffffu, acc[i], 8);
        acc[i] += __shfl_xor_sync(0xffffffffu, acc[i], 16);
    }
    accw += __shfl_xor_sync(0xffffffffu, accw, 8);
    accw += __shfl_xor_sync(0xffffffffu, accw, 16);
    if (q == 0) {   // lanes 0-7 hold full sums for cols ql*8 .. ql*8+7
        float sd = accw;
        const float4* b4 = (const float4*)(bias + ql * 8);
        const float4* t4 = (const float4*)(t + ql * 8);
        float4 b0 = __ldg(b4), b1 = __ldg(b4 + 1);
        float4 t0 = __ldg(t4), t1 = __ldg(t4 + 1);
        float o[8];
        o[0] = acc[0] + b0.x + sd * t0.x;
        o[1] = acc[1] + b0.y + sd * t0.y;
        o[2] = acc[2] + b0.z + sd * t0.z;
        o[3] = acc[3] + b0.w + sd * t0.w;
        o[4] = acc[4] + b1.x + sd * t1.x;
        o[5] = acc[5] + b1.y + sd * t1.y;
        o[6] = acc[6] + b1.z + sd * t1.z;
        o[7] = acc[7] + b1.w + sd * t1.w;
        float4* op = (float4*)(out + (size_t)wid * 64 + ql * 8);
        op[0] = make_float4(o[0], o[1], o[2], o[3]);
        op[1] = make_float4(o[4], o[5], o[6], o[7]);
        #pragma unroll
        for (int i = 0; i < 8; i++) {
            s_sum[wIdx][ql * 8 + i] = o[i];
            s_sq [wIdx][ql * 8 + i] = o[i] * o[i];
        }
    }
    __syncthreads();
    if (tid < 64) {
        float a = 0.f, b = 0.f;
        #pragma unroll
        for (int w = 0; w < 8; w++) { a += s_sum[w][tid]; b += s_sq[w][tid]; }
        int bkt = (blockIdx.x & 31) * 128;
        atomicAdd(&st[bkt + tid], a);
        atomicAdd(&st[bkt + tid + 64], b);
    }
}

// ---------------- aggregation (NC=40, fp32 h) + fused log_softmax + row-sum ----------
__global__ void k_agg40lsm(const float4* __restrict__ h4, const float* __restrict__ bias,
                           const float* __restrict__ t, float* __restrict__ emb,
                           float* __restrict__ out) {
    int wid  = (blockIdx.x * blockDim.x + threadIdx.x) >> 5;
    int lane = threadIdx.x & 31;
    if (wid >= NN) return;
    int half = lane >> 4, hl = lane & 15;
    bool act = hl < 10;
    int st = g_start[wid], deg = g_deg[wid];
    int pairs = deg >> 1;
    int base = st + half;
    float ax = 0.f, ay = 0.f, az = 0.f, aw = 0.f, accw = 0.f;
    int i = 0;
    while (i + 2 <= pairs) {
        int2 ca = __ldg(&g_cw[base + 2 * i]);
        int2 cb = __ldg(&g_cw[base + 2 * i + 2]);
        float wa = __int_as_float(ca.y), wb = __int_as_float(cb.y);
        accw += wa + wb;
        if (act) {
            float4 va = __ldg(h4 + (size_t)ca.x * 10 + hl);
            float4 vb = __ldg(h4 + (size_t)cb.x * 10 + hl);
            ax += wa * va.x; ay += wa * va.y; az += wa * va.z; aw += wa * va.w;
            ax += wb * vb.x; ay += wb * vb.y; az += wb * vb.z; aw += wb * vb.w;
        }
        i += 2;
    }
    if (i < pairs) {
        int2 c = __ldg(&g_cw[base + 2 * i]);
        float w = __int_as_float(c.y);
        accw += w;
        if (act) {
            float4 v = __ldg(h4 + (size_t)c.x * 10 + hl);
            ax += w * v.x; ay += w * v.y; az += w * v.z; aw += w * v.w;
        }
    }
    if ((deg & 1) && half == 0) {          // odd tail edge handled by half 0
        int2 c = __ldg(&g_cw[st + deg - 1]);
        float w = __int_as_float(c.y);
        accw += w;
        if (act) {
            float4 v = __ldg(h4 + (size_t)c.x * 10 + hl);
            ax += w * v.x; ay += w * v.y; az += w * v.z; aw += w * v.w;
        }
    }
    ax += __shfl_down_sync(0xffffffffu, ax, 16);
    ay += __shfl_down_sync(0xffffffffu, ay, 16);
    az += __shfl_down_sync(0xffffffffu, az, 16);
    aw += __shfl_down_sync(0xffffffffu, aw, 16);
    accw += __shfl_down_sync(0xffffffffu, accw, 16);

    bool fin = (half == 0) && act;         // lanes 0-9 hold cols hl*4..hl*4+3
    float4 v = make_float4(0.f, 0.f, 0.f, 0.f);
    if (fin) {
        float sd = accw;
        float4 b4 = __ldg((const float4*)bias + hl);
        float4 t4 = __ldg((const float4*)t + hl);
        v.x = ax + b4.x + sd * t4.x;
        v.y = ay + b4.y + sd * t4.y;
        v.z = az + b4.z + sd * t4.z;
        v.w = aw + b4.w + sd * t4.w;
        ((float4*)emb)[(size_t)wid * 10 + hl] = v;
    }
    float m = fin ? fmaxf(fmaxf(v.x, v.y), fmaxf(v.z, v.w)) : -3.4e38f;
    #pragma unroll
    for (int o = 16; o > 0; o >>= 1) m = fmaxf(m, __shfl_xor_sync(0xffffffffu, m, o));
    float s = fin ? (__expf(v.x - m) + __expf(v.y - m) + __expf(v.z - m) + __expf(v.w - m)) : 0.f;
    #pragma unroll
    for (int o = 16; o > 0; o >>= 1) s += __shfl_xor_sync(0xffffffffu, s, o);
    float lse = m + logf(s);
    if (fin)
        ((float4*)out)[(size_t)wid * 10 + hl] =
            make_float4(v.x - lse, v.y - lse, v.z - lse, v.w - lse);
}

// ---------------- fold BN into next layer's weights (reads 32 stat buckets) ----------
template <int NCN>
__global__ void k_fold(const float* __restrict__ W, const float* __restrict__ g,
                       const float* __restrict__ be, const float* __restrict__ st,
                       float* __restrict__ Wf, float* __restrict__ t) {
    __shared__ float a[64], c[64];
    int tid = threadIdx.x;
    __shared__ float red[128];
    if (tid < 128) {
        float v = 0.f;
        #pragma unroll 8
        for (int b = 0; b < 32; b++) v += st[b * 128 + tid];
        red[tid] = v;
    }
    __syncthreads();
    if (tid < 64) {
        float mean = red[tid] * (1.f / NN);
        float var  = red[tid + 64] * (1.f / NN) - mean * mean;
        float ai = g[tid] * rsqrtf(var + EPSV);
        a[tid] = ai;
        c[tid] = be[tid] - mean * ai;
    }
    __syncthreads();
    for (int i = tid; i < 64 * NCN; i += 256) Wf[i] = a[i / NCN] * W[i];
    if (tid < NCN) {
        float tv = 0.f;
        #pragma unroll
        for (int k = 0; k < 64; k++) tv += c[k] * W[k * NCN + tid];
        t[tid] = tv;
    }
}

// ---------------- launcher ----------------
extern "C" void kernel_launch(void* const* d_in, const int* in_sizes, int n_in,
                              void* d_out, int out_size) {
    const float* x   = (const float*)d_in[0];
    const void*  ei  = d_in[1];                 // int32 or int64, detected on device
    const float* W1  = (const float*)d_in[2];
    const float* b1  = (const float*)d_in[3];
    const float* W2  = (const float*)d_in[4];
    const float* b2  = (const float*)d_in[5];
    const float* W3  = (const float*)d_in[6];
    const float* b3  = (const float*)d_in[7];
    const float* g1  = (const float*)d_in[8];
    const float* be1 = (const float*)d_in[9];
    const float* g2  = (const float*)d_in[10];
    const float* be2 = (const float*)d_in[11];
    float* out = (float*)d_out;

    float *hP, *aP, *W2fP, *W3fP, *t2P, *t3P, *z64P, *s1P, *s2P;
    cudaGetSymbolAddress((void**)&hP,   g_h);
    cudaGetSymbolAddress((void**)&aP,   g_agg);
    cudaGetSymbolAddress((void**)&W2fP, g_W2f);
    cudaGetSymbolAddress((void**)&W3fP, g_W3f);
    cudaGetSymbolAddress((void**)&t2P,  g_t2);
    cudaGetSymbolAddress((void**)&t3P,  g_t3);
    cudaGetSymbolAddress((void**)&z64P, g_zero64);
    cudaGetSymbolAddress((void**)&s1P,  g_stats1);
    cudaGetSymbolAddress((void**)&s2P,  g_stats2);

    // output layout: (out, emb) concatenated
    float* emb = (out_size >= 2 * NN * 40) ? (out + NN * 40) : aP;

    // graph build (single stream)
    k_init  <<<(NN + 255) / 256, 256>>>((const long long*)ei);
    k_degree<<<(EE / 4 + 255) / 256, 256>>>(ei);
    k_scanA <<<NT, 256>>>();
    k_scanC <<<NT, 256>>>();
    k_fill  <<<(EE / 4 + NN + 255) / 256, 256>>>(ei);

    // layer 1 (h in fp16, stats fused into agg)
    k_gemm<64, true><<<(NN + 63) / 64, 256>>>(x, W1, hP);
    k_agg64h  <<<NN / 8, 256>>>((const uint4*)hP, b1, z64P, aP, s1P);
    k_fold<64><<<1, 256>>>(W2, g1, be1, s1P, W2fP, t2P);

    // layer 2 (BN1 folded into W2, h in fp16, stats fused)
    k_gemm<64, true><<<(NN + 63) / 64, 256>>>(aP, W2fP, hP);
    k_agg64h  <<<NN / 8, 256>>>((const uint4*)hP, b2, t2P, aP, s2P);
    k_fold<40><<<1, 256>>>(W3, g2, be2, s2P, W3fP, t3P);

    // layer 3 (BN2 folded into W3, fp32 throughout) -> emb + fused log_softmax -> out
    k_gemm<40, false><<<(NN + 63) / 64, 160>>>(aP, W3fP, hP);
    k_agg40lsm<<<(NN + 7) / 8, 256>>>((const float4*)hP, b3, t3P, emb, out);
}

// round 14
// speedup vs baseline: 1.4727x; 1.0303x over previous
#include <cuda_runtime.h>
#include <cuda_fp16.h>
#include <math.h>

#define NN 100000
#define EE 1600000
#define MM (EE + NN)
#define NT 391           // ceil(NN / 256) scan tiles
#define EPSV 1e-5f

// ---------------- scratch (static device allocations; no cudaMalloc) ----------------
__device__ int   g_is64 = 1;        // detection only ever clears -> stable across replays
__device__ int   g_deg[NN];
__device__ float g_dinv[NN];
__device__ int   g_start[NN];
__device__ int   g_cursor[NN];
__device__ int   g_tilesum[NT];
__device__ int2  g_cw[MM];          // (src, norm-bits) per CSR slot
__device__ __align__(16) float g_h[NN * 64];      // GEMM out: fp16 (L1/2) or fp32 (L3)
__device__ __align__(16) float g_agg[NN * 64];    // agg out: fp16 rows, stride 64 halves
__device__ float g_stats1[32 * 128];  // 32 contention buckets x [sum(64), sumsq(64)]
__device__ float g_stats2[32 * 128];
__device__ float g_W2f[64 * 64];    // BN1-folded W2
__device__ __align__(16) float g_W3f[64 * 40];    // BN2-folded W3
__device__ float g_t2[64];
__device__ __align__(16) float g_t3[64];
__device__ __align__(16) float g_zero64[64];

__device__ __forceinline__ unsigned h2u(__half2 h) {
    return *reinterpret_cast<unsigned*>(&h);
}

// ---------------- graph init + sampled dtype detect ----------------
__global__ void k_init(const long long* __restrict__ p) {
    int i = blockIdx.x * blockDim.x + threadIdx.x;
    if (i < NN) g_deg[i] = 1;                        // self-loop
    if (i < 32 * 128) { g_stats1[i] = 0.f; g_stats2[i] = 0.f; }
    if (i < 64) g_zero64[i] = 0.f;
    if (i < 8192) {
        long long v = p[(size_t)i * 195];            // max idx < EE int64 slots
        if (v < 0 || v >= NN) g_is64 = 0;            // only writes 0: race-free
    }
}

// ---------------- degree: 4 edges per thread ----------------
__global__ void k_degree(const void* __restrict__ ei) {
    int i = blockIdx.x * blockDim.x + threadIdx.x;
    if (i >= EE / 4) return;
    if (g_is64) {
        const longlong2* p = (const longlong2*)ei;
        longlong2 a = p[EE / 2 + i * 2];
        longlong2 b = p[EE / 2 + i * 2 + 1];
        if ((unsigned long long)a.x < NN) atomicAdd(&g_deg[(int)a.x], 1);
        if ((unsigned long long)a.y < NN) atomicAdd(&g_deg[(int)a.y], 1);
        if ((unsigned long long)b.x < NN) atomicAdd(&g_deg[(int)b.x], 1);
        if ((unsigned long long)b.y < NN) atomicAdd(&g_deg[(int)b.y], 1);
    } else {
        int4 v = ((const int4*)ei)[EE / 4 + i];
        if ((unsigned)v.x < NN) atomicAdd(&g_deg[v.x], 1);
        if ((unsigned)v.y < NN) atomicAdd(&g_deg[v.y], 1);
        if ((unsigned)v.z < NN) atomicAdd(&g_deg[v.z], 1);
        if ((unsigned)v.w < NN) atomicAdd(&g_deg[v.w], 1);
    }
}

// ---------------- scanA: 391 blocks x 256 thr, 1 node/thread + fused dinv ----------
__global__ void k_scanA() {
    int tid = threadIdx.x;
    int idx = blockIdx.x * 256 + tid;
    int d = 0;
    if (idx < NN) {
        d = g_deg[idx];
        g_dinv[idx] = rsqrtf((float)d);
    }
    __shared__ int sh[256];
    sh[tid] = d;
    __syncthreads();
    for (int o = 128; o > 0; o >>= 1) {
        if (tid < o) sh[tid] += sh[tid + o];
        __syncthreads();
    }
    if (tid == 0) g_tilesum[blockIdx.x] = sh[0];
}

// ---------------- scanC: lookback + warp-shuffle scan (2 syncthreads) ----------------
__global__ void k_scanC() {
    int tid = threadIdx.x;
    int lane = tid & 31, wrp = tid >> 5;
    __shared__ int s_off;
    __shared__ int wsum[8];
    if (tid < 32) {
        int v = 0;
        for (int j = tid; j < blockIdx.x; j += 32) v += g_tilesum[j];
        #pragma unroll
        for (int o = 16; o > 0; o >>= 1) v += __shfl_xor_sync(0xffffffffu, v, o);
        if (tid == 0) s_off = v;
    }
    int idx = blockIdx.x * 256 + tid;
    int d = (idx < NN) ? g_deg[idx] : 0;
    int v = d;                           // warp inclusive scan
    #pragma unroll
    for (int o = 1; o < 32; o <<= 1) {
        int u = __shfl_up_sync(0xffffffffu, v, o);
        if (lane >= o) v += u;
    }
    if (lane == 31) wsum[wrp] = v;
    __syncthreads();
    if (tid < 8) {                       // exclusive scan of 8 warp totals
        int x = wsum[tid];
        int y = x;
        #pragma unroll
        for (int o = 1; o < 8; o <<= 1) {
            int u = __shfl_up_sync(0xffu, y, o);
            if (tid >= o) y += u;
        }
        wsum[tid] = y - x;
    }
    __syncthreads();
    if (idx < NN) {
        int p = s_off + wsum[wrp] + v - d;   // exclusive position
        g_start[idx] = p;
        g_cursor[idx] = p;
    }
}

// CSR fill; 4 edges per thread, self-loops appended. (row-sum computed in agg)
__device__ __forceinline__ void fill_one(int s, int d) {
    float w = g_dinv[s] * g_dinv[d];
    int pos = atomicAdd(&g_cursor[d], 1);
    g_cw[pos] = make_int2(s, __float_as_int(w));
}

__global__ void k_fill(const void* __restrict__ ei) {
    int i = blockIdx.x * blockDim.x + threadIdx.x;
    if (i < EE / 4) {
        if (g_is64) {
            const longlong2* p = (const longlong2*)ei;
            longlong2 sa = p[i * 2],           sb = p[i * 2 + 1];
            longlong2 da = p[EE / 2 + i * 2],  db = p[EE / 2 + i * 2 + 1];
            if ((unsigned long long)sa.x < NN && (unsigned long long)da.x < NN)
                fill_one((int)sa.x, (int)da.x);
            if ((unsigned long long)sa.y < NN && (unsigned long long)da.y < NN)
                fill_one((int)sa.y, (int)da.y);
            if ((unsigned long long)sb.x < NN && (unsigned long long)db.x < NN)
                fill_one((int)sb.x, (int)db.x);
            if ((unsigned long long)sb.y < NN && (unsigned long long)db.y < NN)
                fill_one((int)sb.y, (int)db.y);
        } else {
            int4 sv = ((const int4*)ei)[i];
            int4 dv = ((const int4*)ei)[EE / 4 + i];
            if ((unsigned)sv.x < NN && (unsigned)dv.x < NN) fill_one(sv.x, dv.x);
            if ((unsigned)sv.y < NN && (unsigned)dv.y < NN) fill_one(sv.y, dv.y);
            if ((unsigned)sv.z < NN && (unsigned)dv.z < NN) fill_one(sv.z, dv.z);
            if ((unsigned)sv.w < NN && (unsigned)dv.w < NN) fill_one(sv.w, dv.w);
        }
    } else {
        int n = i - EE / 4;
        if (n < NN) fill_one(n, n);        // self-loop
    }
}

// ---------------- GEMM: out[N x NC] = in[N x 64] @ W[64 x NC] ----------------
// HIN: input rows fp16 (stride 64 halves); else fp32 (stride 64 floats).
// HOUT: output fp16 (stride 64 halves); else fp32 (stride NC floats).
template <int NC, bool HIN, bool HOUT>
__global__ void k_gemm(const void* __restrict__ in, const float* __restrict__ W,
                       void* __restrict__ out) {
    __shared__ float XsT[64 * 68];   // [k][row], padded
    __shared__ float Ws[64 * NC];    // [k][j]
    const int nth = (NC / 4) * 16;
    int tid = threadIdx.x;
    int row0 = blockIdx.x * 64;

    for (int i = tid; i < 64 * NC / 4; i += nth)
        ((float4*)Ws)[i] = ((const float4*)W)[i];

    for (int i = tid; i < 64 * 16; i += nth) {
        int r = i & 63, k4 = i >> 6;
        int gr = row0 + r;
        float4 v = make_float4(0.f, 0.f, 0.f, 0.f);
        if (gr < NN) {
            if (HIN) {
                uint2 u = ((const uint2*)((const __half*)in + (size_t)gr * 64))[k4];
                float2 f0 = __half22float2(*(const __half2*)&u.x);
                float2 f1 = __half22float2(*(const __half2*)&u.y);
                v = make_float4(f0.x, f0.y, f1.x, f1.y);
            } else {
                v = ((const float4*)in)[(size_t)gr * 16 + k4];
            }
        }
        XsT[(k4 * 4 + 0) * 68 + r] = v.x;
        XsT[(k4 * 4 + 1) * 68 + r] = v.y;
        XsT[(k4 * 4 + 2) * 68 + r] = v.z;
        XsT[(k4 * 4 + 3) * 68 + r] = v.w;
    }
    __syncthreads();

    int tc = tid % (NC / 4), tr = tid / (NC / 4);
    int c0 = tc * 4, r0 = tr * 4;
    float acc[4][4];
    #pragma unroll
    for (int i = 0; i < 4; i++)
        #pragma unroll
        for (int j = 0; j < 4; j++) acc[i][j] = 0.f;

    #pragma unroll 8
    for (int k = 0; k < 64; k++) {
        float4 b = *(const float4*)&Ws[k * NC + c0];
        float4 a = *(const float4*)&XsT[k * 68 + r0];
        acc[0][0] += a.x * b.x; acc[0][1] += a.x * b.y; acc[0][2] += a.x * b.z; acc[0][3] += a.x * b.w;
        acc[1][0] += a.y * b.x; acc[1][1] += a.y * b.y; acc[1][2] += a.y * b.z; acc[1][3] += a.y * b.w;
        acc[2][0] += a.z * b.x; acc[2][1] += a.z * b.y; acc[2][2] += a.z * b.z; acc[2][3] += a.z * b.w;
        acc[3][0] += a.w * b.x; acc[3][1] += a.w * b.y; acc[3][2] += a.w * b.z; acc[3][3] += a.w * b.w;
    }

    #pragma unroll
    for (int i = 0; i < 4; i++) {
        int gr = row0 + r0 + i;
        if (gr < NN) {
            if (HOUT) {
                __half2 h0 = __floats2half2_rn(acc[i][0], acc[i][1]);
                __half2 h1 = __floats2half2_rn(acc[i][2], acc[i][3]);
                __half2* o2 = (__half2*)((__half*)out + (size_t)gr * 64 + c0);
                o2[0] = h0; o2[1] = h1;
            } else {
                *(float4*)&((float*)out)[(size_t)gr * NC + c0] =
                    make_float4(acc[i][0], acc[i][1], acc[i][2], acc[i][3]);
            }
        }
    }
}

// ---------------- aggregation (NC=64, fp16 h) + fused BN stats, fp16 output --------
// Stats computed from fp32 values BEFORE fp16 rounding of the output.
__global__ void __launch_bounds__(256)
k_agg64h(const uint4* __restrict__ h4, const float* __restrict__ bias,
         const float* __restrict__ t, __half* __restrict__ out,
         float* __restrict__ st) {
    __shared__ float s_sum[8][64];
    __shared__ float s_sq[8][64];
    int tid = threadIdx.x;
    int wIdx = tid >> 5;
    int wid  = blockIdx.x * 8 + wIdx;      // always < NN
    int lane = tid & 31;
    int q = lane >> 3, ql = lane & 7;
    int stt = g_start[wid], en = stt + g_deg[wid];
    float acc[8];
    float accw = 0.f;                      // row-sum of norms
    #pragma unroll
    for (int i = 0; i < 8; i++) acc[i] = 0.f;

    #pragma unroll 2
    for (int e = stt + q; e < en; e += 4) {
        int2 c = __ldg(&g_cw[e]);
        uint4 v = __ldg(h4 + (size_t)c.x * 8 + ql);   // 8 halves of the row
        float w = __int_as_float(c.y);
        accw += w;
        float2 f;
        f = __half22float2(*(const __half2*)&v.x); acc[0] += w * f.x; acc[1] += w * f.y;
        f = __half22float2(*(const __half2*)&v.y); acc[2] += w * f.x; acc[3] += w * f.y;
        f = __half22float2(*(const __half2*)&v.z); acc[4] += w * f.x; acc[5] += w * f.y;
        f = __half22float2(*(const __half2*)&v.w); acc[6] += w * f.x; acc[7] += w * f.y;
    }
    #pragma unroll
    for (int i = 0; i < 8; i++) {
        acc[i] += __shfl_xor_sync(0xffffffffu, acc[i], 8);
        acc[i] += __shfl_xor_sync(0xffffffffu, acc[i], 16);
    }
    accw += __shfl_xor_sync(0xffffffffu, accw, 8);
    accw += __shfl_xor_sync(0xffffffffu, accw, 16);
    if (q == 0) {   // lanes 0-7 hold full sums for cols ql*8 .. ql*8+7
        float sd = accw;
        const float4* b4 = (const float4*)(bias + ql * 8);
        const float4* t4 = (const float4*)(t + ql * 8);
        float4 b0 = __ldg(b4), b1 = __ldg(b4 + 1);
        float4 t0 = __ldg(t4), t1 = __ldg(t4 + 1);
        float o[8];
        o[0] = acc[0] + b0.x + sd * t0.x;
        o[1] = acc[1] + b0.y + sd * t0.y;
        o[2] = acc[2] + b0.z + sd * t0.z;
        o[3] = acc[3] + b0.w + sd * t0.w;
        o[4] = acc[4] + b1.x + sd * t1.x;
        o[5] = acc[5] + b1.y + sd * t1.y;
        o[6] = acc[6] + b1.z + sd * t1.z;
        o[7] = acc[7] + b1.w + sd * t1.w;
        uint4 pk;
        pk.x = h2u(__floats2half2_rn(o[0], o[1]));
        pk.y = h2u(__floats2half2_rn(o[2], o[3]));
        pk.z = h2u(__floats2half2_rn(o[4], o[5]));
        pk.w = h2u(__floats2half2_rn(o[6], o[7]));
        *(uint4*)(out + (size_t)wid * 64 + ql * 8) = pk;
        #pragma unroll
        for (int i = 0; i < 8; i++) {
            s_sum[wIdx][ql * 8 + i] = o[i];
            s_sq [wIdx][ql * 8 + i] = o[i] * o[i];
        }
    }
    __syncthreads();
    if (tid < 64) {
        float a = 0.f, b = 0.f;
        #pragma unroll
        for (int w = 0; w < 8; w++) { a += s_sum[w][tid]; b += s_sq[w][tid]; }
        int bkt = (blockIdx.x & 31) * 128;
        atomicAdd(&st[bkt + tid], a);
        atomicAdd(&st[bkt + tid + 64], b);
    }
}

// ---------------- aggregation (NC=40, fp32 h) + fused log_softmax + row-sum ----------
__global__ void k_agg40lsm(const float4* __restrict__ h4, const float* __restrict__ bias,
                           const float* __restrict__ t, float* __restrict__ emb,
                           float* __restrict__ out) {
    int wid  = (blockIdx.x * blockDim.x + threadIdx.x) >> 5;
    int lane = threadIdx.x & 31;
    if (wid >= NN) return;
    int half = lane >> 4, hl = lane & 15;
    bool act = hl < 10;
    int st = g_start[wid], deg = g_deg[wid];
    int pairs = deg >> 1;
    int base = st + half;
    float ax = 0.f, ay = 0.f, az = 0.f, aw = 0.f, accw = 0.f;
    int i = 0;
    while (i + 2 <= pairs) {
        int2 ca = __ldg(&g_cw[base + 2 * i]);
        int2 cb = __ldg(&g_cw[base + 2 * i + 2]);
        float wa = __int_as_float(ca.y), wb = __int_as_float(cb.y);
        accw += wa + wb;
        if (act) {
            float4 va = __ldg(h4 + (size_t)ca.x * 10 + hl);
            float4 vb = __ldg(h4 + (size_t)cb.x * 10 + hl);
            ax += wa * va.x; ay += wa * va.y; az += wa * va.z; aw += wa * va.w;
            ax += wb * vb.x; ay += wb * vb.y; az += wb * vb.z; aw += wb * vb.w;
        }
        i += 2;
    }
    if (i < pairs) {
        int2 c = __ldg(&g_cw[base + 2 * i]);
        float w = __int_as_float(c.y);
        accw += w;
        if (act) {
            float4 v = __ldg(h4 + (size_t)c.x * 10 + hl);
            ax += w * v.x; ay += w * v.y; az += w * v.z; aw += w * v.w;
        }
    }
    if ((deg & 1) && half == 0) {          // odd tail edge handled by half 0
        int2 c = __ldg(&g_cw[st + deg - 1]);
        float w = __int_as_float(c.y);
        accw += w;
        if (act) {
            float4 v = __ldg(h4 + (size_t)c.x * 10 + hl);
            ax += w * v.x; ay += w * v.y; az += w * v.z; aw += w * v.w;
        }
    }
    ax += __shfl_down_sync(0xffffffffu, ax, 16);
    ay += __shfl_down_sync(0xffffffffu, ay, 16);
    az += __shfl_down_sync(0xffffffffu, az, 16);
    aw += __shfl_down_sync(0xffffffffu, aw, 16);
    accw += __shfl_down_sync(0xffffffffu, accw, 16);

    bool fin = (half == 0) && act;         // lanes 0-9 hold cols hl*4..hl*4+3
    float4 v = make_float4(0.f, 0.f, 0.f, 0.f);
    if (fin) {
        float sd = accw;
        float4 b4 = __ldg((const float4*)bias + hl);
        float4 t4 = __ldg((const float4*)t + hl);
        v.x = ax + b4.x + sd * t4.x;
        v.y = ay + b4.y + sd * t4.y;
        v.z = az + b4.z + sd * t4.z;
        v.w = aw + b4.w + sd * t4.w;
        ((float4*)emb)[(size_t)wid * 10 + hl] = v;
    }
    float m = fin ? fmaxf(fmaxf(v.x, v.y), fmaxf(v.z, v.w)) : -3.4e38f;
    #pragma unroll
    for (int o = 16; o > 0; o >>= 1) m = fmaxf(m, __shfl_xor_sync(0xffffffffu, m, o));
    float s = fin ? (__expf(v.x - m) + __expf(v.y - m) + __expf(v.z - m) + __expf(v.w - m)) : 0.f;
    #pragma unroll
    for (int o = 16; o > 0; o >>= 1) s += __shfl_xor_sync(0xffffffffu, s, o);
    float lse = m + logf(s);
    if (fin)
        ((float4*)out)[(size_t)wid * 10 + hl] =
            make_float4(v.x - lse, v.y - lse, v.z - lse, v.w - lse);
}

// ---------------- fold BN into next layer's weights (reads 32 stat buckets) ----------
template <int NCN>
__global__ void k_fold(const float* __restrict__ W, const float* __restrict__ g,
                       const float* __restrict__ be, const float* __restrict__ st,
                       float* __restrict__ Wf, float* __restrict__ t) {
    __shared__ float a[64], c[64];
    int tid = threadIdx.x;
    __shared__ float red[128];
    if (tid < 128) {
        float v = 0.f;
        #pragma unroll 8
        for (int b = 0; b < 32; b++) v += st[b * 128 + tid];
        red[tid] = v;
    }
    __syncthreads();
    if (tid < 64) {
        float mean = red[tid] * (1.f / NN);
        float var  = red[tid + 64] * (1.f / NN) - mean * mean;
        float ai = g[tid] * rsqrtf(var + EPSV);
        a[tid] = ai;
        c[tid] = be[tid] - mean * ai;
    }
    __syncthreads();
    for (int i = tid; i < 64 * NCN; i += 256) Wf[i] = a[i / NCN] * W[i];
    if (tid < NCN) {
        float tv = 0.f;
        #pragma unroll
        for (int k = 0; k < 64; k++) tv += c[k] * W[k * NCN + tid];
        t[tid] = tv;
    }
}

// ---------------- launcher ----------------
extern "C" void kernel_launch(void* const* d_in, const int* in_sizes, int n_in,
                              void* d_out, int out_size) {
    const float* x   = (const float*)d_in[0];
    const void*  ei  = d_in[1];                 // int32 or int64, detected on device
    const float* W1  = (const float*)d_in[2];
    const float* b1  = (const float*)d_in[3];
    const float* W2  = (const float*)d_in[4];
    const float* b2  = (const float*)d_in[5];
    const float* W3  = (const float*)d_in[6];
    const float* b3  = (const float*)d_in[7];
    const float* g1  = (const float*)d_in[8];
    const float* be1 = (const float*)d_in[9];
    const float* g2  = (const float*)d_in[10];
    const float* be2 = (const float*)d_in[11];
    float* out = (float*)d_out;

    float *hP, *aP, *W2fP, *W3fP, *t2P, *t3P, *z64P, *s1P, *s2P;
    cudaGetSymbolAddress((void**)&hP,   g_h);
    cudaGetSymbolAddress((void**)&aP,   g_agg);
    cudaGetSymbolAddress((void**)&W2fP, g_W2f);
    cudaGetSymbolAddress((void**)&W3fP, g_W3f);
    cudaGetSymbolAddress((void**)&t2P,  g_t2);
    cudaGetSymbolAddress((void**)&t3P,  g_t3);
    cudaGetSymbolAddress((void**)&z64P, g_zero64);
    cudaGetSymbolAddress((void**)&s1P,  g_stats1);
    cudaGetSymbolAddress((void**)&s2P,  g_stats2);

    // output layout: (out, emb) concatenated
    float* emb = (out_size >= 2 * NN * 40) ? (out + NN * 40) : aP;

    // graph build (single stream)
    k_init  <<<(NN + 255) / 256, 256>>>((const long long*)ei);
    k_degree<<<(EE / 4 + 255) / 256, 256>>>(ei);
    k_scanA <<<NT, 256>>>();
    k_scanC <<<NT, 256>>>();
    k_fill  <<<(EE / 4 + NN + 255) / 256, 256>>>(ei);

    // layer 1 (h fp16, agg out fp16, stats fused)
    k_gemm<64, false, true><<<(NN + 63) / 64, 256>>>(x, W1, hP);
    k_agg64h  <<<NN / 8, 256>>>((const uint4*)hP, b1, z64P, (__half*)aP, s1P);
    k_fold<64><<<1, 256>>>(W2, g1, be1, s1P, W2fP, t2P);

    // layer 2 (BN1 folded into W2; fp16 in, fp16 h, fp16 agg out, stats fused)
    k_gemm<64, true, true><<<(NN + 63) / 64, 256>>>(aP, W2fP, hP);
    k_agg64h  <<<NN / 8, 256>>>((const uint4*)hP, b2, t2P, (__half*)aP, s2P);
    k_fold<40><<<1, 256>>>(W3, g2, be2, s2P, W3fP, t3P);

    // layer 3 (BN2 folded into W3; fp16 in, fp32 h) -> emb + fused log_softmax -> out
    k_gemm<40, true, false><<<(NN + 63) / 64, 160>>>(aP, W3fP, hP);
    k_agg40lsm<<<(NN + 7) / 8, 256>>>((const float4*)hP, b3, t3P, emb, out);
}

// round 15
// speedup vs baseline: 1.4793x; 1.0045x over previous
#include <cuda_runtime.h>
#include <cuda_fp16.h>
#include <math.h>

#define NN 100000
#define EE 1600000
#define MM (EE + NN)
#define NT 391           // ceil(NN / 256) scan tiles
#define EPSV 1e-5f

// ---------------- scratch (static device allocations; no cudaMalloc) ----------------
__device__ int   g_is64 = 1;        // detection only ever clears -> stable across replays
__device__ int   g_deg[NN];
__device__ float g_dinv[NN];
__device__ int   g_start[NN];
__device__ int   g_cursor[NN];
__device__ int   g_tilesum[NT];
__device__ int2  g_cw[MM];          // (src, norm-bits) per CSR slot
__device__ __align__(16) float g_h[NN * 64];      // GEMM out: fp16 rows, stride 64 halves
__device__ __align__(16) float g_agg[NN * 64];    // agg out: fp16 rows, stride 64 halves
__device__ float g_stats1[32 * 128];  // 32 contention buckets x [sum(64), sumsq(64)]
__device__ float g_stats2[32 * 128];
__device__ float g_W2f[64 * 64];    // BN1-folded W2
__device__ __align__(16) float g_W3f[64 * 40];    // BN2-folded W3
__device__ float g_t2[64];
__device__ __align__(16) float g_t3[64];
__device__ __align__(16) float g_zero64[64];

__device__ __forceinline__ unsigned h2u(__half2 h) {
    return *reinterpret_cast<unsigned*>(&h);
}

// ---------------- graph init + sampled dtype detect ----------------
__global__ void k_init(const long long* __restrict__ p) {
    int i = blockIdx.x * blockDim.x + threadIdx.x;
    if (i < NN) g_deg[i] = 1;                        // self-loop
    if (i < 32 * 128) { g_stats1[i] = 0.f; g_stats2[i] = 0.f; }
    if (i < 64) g_zero64[i] = 0.f;
    if (i < 8192) {
        long long v = p[(size_t)i * 195];            // max idx < EE int64 slots
        if (v < 0 || v >= NN) g_is64 = 0;            // only writes 0: race-free
    }
}

// ---------------- degree: 4 edges per thread ----------------
__global__ void k_degree(const void* __restrict__ ei) {
    int i = blockIdx.x * blockDim.x + threadIdx.x;
    if (i >= EE / 4) return;
    if (g_is64) {
        const longlong2* p = (const longlong2*)ei;
        longlong2 a = p[EE / 2 + i * 2];
        longlong2 b = p[EE / 2 + i * 2 + 1];
        if ((unsigned long long)a.x < NN) atomicAdd(&g_deg[(int)a.x], 1);
        if ((unsigned long long)a.y < NN) atomicAdd(&g_deg[(int)a.y], 1);
        if ((unsigned long long)b.x < NN) atomicAdd(&g_deg[(int)b.x], 1);
        if ((unsigned long long)b.y < NN) atomicAdd(&g_deg[(int)b.y], 1);
    } else {
        int4 v = ((const int4*)ei)[EE / 4 + i];
        if ((unsigned)v.x < NN) atomicAdd(&g_deg[v.x], 1);
        if ((unsigned)v.y < NN) atomicAdd(&g_deg[v.y], 1);
        if ((unsigned)v.z < NN) atomicAdd(&g_deg[v.z], 1);
        if ((unsigned)v.w < NN) atomicAdd(&g_deg[v.w], 1);
    }
}

// ---------------- scanA: 391 blocks x 256 thr, 1 node/thread + fused dinv ----------
__global__ void k_scanA() {
    int tid = threadIdx.x;
    int idx = blockIdx.x * 256 + tid;
    int d = 0;
    if (idx < NN) {
        d = g_deg[idx];
        g_dinv[idx] = rsqrtf((float)d);
    }
    __shared__ int sh[256];
    sh[tid] = d;
    __syncthreads();
    for (int o = 128; o > 0; o >>= 1) {
        if (tid < o) sh[tid] += sh[tid + o];
        __syncthreads();
    }
    if (tid == 0) g_tilesum[blockIdx.x] = sh[0];
}

// ---------------- scanC: lookback + warp-shuffle scan (2 syncthreads) ----------------
__global__ void k_scanC() {
    int tid = threadIdx.x;
    int lane = tid & 31, wrp = tid >> 5;
    __shared__ int s_off;
    __shared__ int wsum[8];
    if (tid < 32) {
        int v = 0;
        for (int j = tid; j < blockIdx.x; j += 32) v += g_tilesum[j];
        #pragma unroll
        for (int o = 16; o > 0; o >>= 1) v += __shfl_xor_sync(0xffffffffu, v, o);
        if (tid == 0) s_off = v;
    }
    int idx = blockIdx.x * 256 + tid;
    int d = (idx < NN) ? g_deg[idx] : 0;
    int v = d;                           // warp inclusive scan
    #pragma unroll
    for (int o = 1; o < 32; o <<= 1) {
        int u = __shfl_up_sync(0xffffffffu, v, o);
        if (lane >= o) v += u;
    }
    if (lane == 31) wsum[wrp] = v;
    __syncthreads();
    if (tid < 8) {                       // exclusive scan of 8 warp totals
        int x = wsum[tid];
        int y = x;
        #pragma unroll
        for (int o = 1; o < 8; o <<= 1) {
            int u = __shfl_up_sync(0xffu, y, o);
            if (tid >= o) y += u;
        }
        wsum[tid] = y - x;
    }
    __syncthreads();
    if (idx < NN) {
        int p = s_off + wsum[wrp] + v - d;   // exclusive position
        g_start[idx] = p;
        g_cursor[idx] = p;
    }
}

// CSR fill; 4 edges per thread, self-loops appended. (row-sum computed in agg)
__device__ __forceinline__ void fill_one(int s, int d) {
    float w = g_dinv[s] * g_dinv[d];
    int pos = atomicAdd(&g_cursor[d], 1);
    g_cw[pos] = make_int2(s, __float_as_int(w));
}

__global__ void k_fill(const void* __restrict__ ei) {
    int i = blockIdx.x * blockDim.x + threadIdx.x;
    if (i < EE / 4) {
        if (g_is64) {
            const longlong2* p = (const longlong2*)ei;
            longlong2 sa = p[i * 2],           sb = p[i * 2 + 1];
            longlong2 da = p[EE / 2 + i * 2],  db = p[EE / 2 + i * 2 + 1];
            if ((unsigned long long)sa.x < NN && (unsigned long long)da.x < NN)
                fill_one((int)sa.x, (int)da.x);
            if ((unsigned long long)sa.y < NN && (unsigned long long)da.y < NN)
                fill_one((int)sa.y, (int)da.y);
            if ((unsigned long long)sb.x < NN && (unsigned long long)db.x < NN)
                fill_one((int)sb.x, (int)db.x);
            if ((unsigned long long)sb.y < NN && (unsigned long long)db.y < NN)
                fill_one((int)sb.y, (int)db.y);
        } else {
            int4 sv = ((const int4*)ei)[i];
            int4 dv = ((const int4*)ei)[EE / 4 + i];
            if ((unsigned)sv.x < NN && (unsigned)dv.x < NN) fill_one(sv.x, dv.x);
            if ((unsigned)sv.y < NN && (unsigned)dv.y < NN) fill_one(sv.y, dv.y);
            if ((unsigned)sv.z < NN && (unsigned)dv.z < NN) fill_one(sv.z, dv.z);
            if ((unsigned)sv.w < NN && (unsigned)dv.w < NN) fill_one(sv.w, dv.w);
        }
    } else {
        int n = i - EE / 4;
        if (n < NN) fill_one(n, n);        // self-loop
    }
}

// ---------------- GEMM: out[N x NC] = in[N x 64] @ W[64 x NC] ----------------
// HIN: input rows fp16 (stride 64 halves); else fp32 (stride 64 floats).
// HOUT: output fp16 (stride 64 halves); else fp32 (stride NC floats).
template <int NC, bool HIN, bool HOUT>
__global__ void k_gemm(const void* __restrict__ in, const float* __restrict__ W,
                       void* __restrict__ out) {
    __shared__ float XsT[64 * 68];   // [k][row], padded
    __shared__ float Ws[64 * NC];    // [k][j]
    const int nth = (NC / 4) * 16;
    int tid = threadIdx.x;
    int row0 = blockIdx.x * 64;

    for (int i = tid; i < 64 * NC / 4; i += nth)
        ((float4*)Ws)[i] = ((const float4*)W)[i];

    for (int i = tid; i < 64 * 16; i += nth) {
        int r = i & 63, k4 = i >> 6;
        int gr = row0 + r;
        float4 v = make_float4(0.f, 0.f, 0.f, 0.f);
        if (gr < NN) {
            if (HIN) {
                uint2 u = ((const uint2*)((const __half*)in + (size_t)gr * 64))[k4];
                float2 f0 = __half22float2(*(const __half2*)&u.x);
                float2 f1 = __half22float2(*(const __half2*)&u.y);
                v = make_float4(f0.x, f0.y, f1.x, f1.y);
            } else {
                v = ((const float4*)in)[(size_t)gr * 16 + k4];
            }
        }
        XsT[(k4 * 4 + 0) * 68 + r] = v.x;
        XsT[(k4 * 4 + 1) * 68 + r] = v.y;
        XsT[(k4 * 4 + 2) * 68 + r] = v.z;
        XsT[(k4 * 4 + 3) * 68 + r] = v.w;
    }
    __syncthreads();

    int tc = tid % (NC / 4), tr = tid / (NC / 4);
    int c0 = tc * 4, r0 = tr * 4;
    float acc[4][4];
    #pragma unroll
    for (int i = 0; i < 4; i++)
        #pragma unroll
        for (int j = 0; j < 4; j++) acc[i][j] = 0.f;

    #pragma unroll 8
    for (int k = 0; k < 64; k++) {
        float4 b = *(const float4*)&Ws[k * NC + c0];
        float4 a = *(const float4*)&XsT[k * 68 + r0];
        acc[0][0] += a.x * b.x; acc[0][1] += a.x * b.y; acc[0][2] += a.x * b.z; acc[0][3] += a.x * b.w;
        acc[1][0] += a.y * b.x; acc[1][1] += a.y * b.y; acc[1][2] += a.y * b.z; acc[1][3] += a.y * b.w;
        acc[2][0] += a.z * b.x; acc[2][1] += a.z * b.y; acc[2][2] += a.z * b.z; acc[2][3] += a.z * b.w;
        acc[3][0] += a.w * b.x; acc[3][1] += a.w * b.y; acc[3][2] += a.w * b.z; acc[3][3] += a.w * b.w;
    }

    #pragma unroll
    for (int i = 0; i < 4; i++) {
        int gr = row0 + r0 + i;
        if (gr < NN) {
            if (HOUT) {
                __half2 h0 = __floats2half2_rn(acc[i][0], acc[i][1]);
                __half2 h1 = __floats2half2_rn(acc[i][2], acc[i][3]);
                __half2* o2 = (__half2*)((__half*)out + (size_t)gr * 64 + c0);
                o2[0] = h0; o2[1] = h1;
            } else {
                *(float4*)&((float*)out)[(size_t)gr * NC + c0] =
                    make_float4(acc[i][0], acc[i][1], acc[i][2], acc[i][3]);
            }
        }
    }
}

// ---------------- aggregation (NC=64, fp16 h) + fused BN stats, fp16 output --------
// Stats computed from fp32 values BEFORE fp16 rounding of the output.
__global__ void __launch_bounds__(256)
k_agg64h(const uint4* __restrict__ h4, const float* __restrict__ bias,
         const float* __restrict__ t, __half* __restrict__ out,
         float* __restrict__ st) {
    __shared__ float s_sum[8][64];
    __shared__ float s_sq[8][64];
    int tid = threadIdx.x;
    int wIdx = tid >> 5;
    int wid  = blockIdx.x * 8 + wIdx;      // always < NN
    int lane = tid & 31;
    int q = lane >> 3, ql = lane & 7;
    int stt = g_start[wid], en = stt + g_deg[wid];
    float acc[8];
    float accw = 0.f;                      // row-sum of norms
    #pragma unroll
    for (int i = 0; i < 8; i++) acc[i] = 0.f;

    #pragma unroll 2
    for (int e = stt + q; e < en; e += 4) {
        int2 c = __ldg(&g_cw[e]);
        uint4 v = __ldg(h4 + (size_t)c.x * 8 + ql);   // 8 halves of the row
        float w = __int_as_float(c.y);
        accw += w;
        float2 f;
        f = __half22float2(*(const __half2*)&v.x); acc[0] += w * f.x; acc[1] += w * f.y;
        f = __half22float2(*(const __half2*)&v.y); acc[2] += w * f.x; acc[3] += w * f.y;
        f = __half22float2(*(const __half2*)&v.z); acc[4] += w * f.x; acc[5] += w * f.y;
        f = __half22float2(*(const __half2*)&v.w); acc[6] += w * f.x; acc[7] += w * f.y;
    }
    #pragma unroll
    for (int i = 0; i < 8; i++) {
        acc[i] += __shfl_xor_sync(0xffffffffu, acc[i], 8);
        acc[i] += __shfl_xor_sync(0xffffffffu, acc[i], 16);
    }
    accw += __shfl_xor_sync(0xffffffffu, accw, 8);
    accw += __shfl_xor_sync(0xffffffffu, accw, 16);
    if (q == 0) {   // lanes 0-7 hold full sums for cols ql*8 .. ql*8+7
        float sd = accw;
        const float4* b4 = (const float4*)(bias + ql * 8);
        const float4* t4 = (const float4*)(t + ql * 8);
        float4 b0 = __ldg(b4), b1 = __ldg(b4 + 1);
        float4 t0 = __ldg(t4), t1 = __ldg(t4 + 1);
        float o[8];
        o[0] = acc[0] + b0.x + sd * t0.x;
        o[1] = acc[1] + b0.y + sd * t0.y;
        o[2] = acc[2] + b0.z + sd * t0.z;
        o[3] = acc[3] + b0.w + sd * t0.w;
        o[4] = acc[4] + b1.x + sd * t1.x;
        o[5] = acc[5] + b1.y + sd * t1.y;
        o[6] = acc[6] + b1.z + sd * t1.z;
        o[7] = acc[7] + b1.w + sd * t1.w;
        uint4 pk;
        pk.x = h2u(__floats2half2_rn(o[0], o[1]));
        pk.y = h2u(__floats2half2_rn(o[2], o[3]));
        pk.z = h2u(__floats2half2_rn(o[4], o[5]));
        pk.w = h2u(__floats2half2_rn(o[6], o[7]));
        *(uint4*)(out + (size_t)wid * 64 + ql * 8) = pk;
        #pragma unroll
        for (int i = 0; i < 8; i++) {
            s_sum[wIdx][ql * 8 + i] = o[i];
            s_sq [wIdx][ql * 8 + i] = o[i] * o[i];
        }
    }
    __syncthreads();
    if (tid < 64) {
        float a = 0.f, b = 0.f;
        #pragma unroll
        for (int w = 0; w < 8; w++) { a += s_sum[w][tid]; b += s_sq[w][tid]; }
        int bkt = (blockIdx.x & 31) * 128;
        atomicAdd(&st[bkt + tid], a);
        atomicAdd(&st[bkt + tid + 64], b);
    }
}

// ---------------- layer-3 aggregation (fp16 h, 40 valid cols of 64) + log_softmax ----
// Quarter-warp uint4 gather identical to k_agg64h; cols 40-63 are stale fp16
// (finite) and are accumulated then discarded. Epilogue on lanes 0-4 (40 cols).
__global__ void k_agg40lsmh(const uint4* __restrict__ h4, const float* __restrict__ bias,
                            const float* __restrict__ t, float* __restrict__ emb,
                            float* __restrict__ out) {
    int wid  = (blockIdx.x * blockDim.x + threadIdx.x) >> 5;
    int lane = threadIdx.x & 31;
    if (wid >= NN) return;
    int q = lane >> 3, ql = lane & 7;
    int stt = g_start[wid], en = stt + g_deg[wid];
    float acc[8];
    float accw = 0.f;
    #pragma unroll
    for (int i = 0; i < 8; i++) acc[i] = 0.f;

    #pragma unroll 2
    for (int e = stt + q; e < en; e += 4) {
        int2 c = __ldg(&g_cw[e]);
        uint4 v = __ldg(h4 + (size_t)c.x * 8 + ql);
        float w = __int_as_float(c.y);
        accw += w;
        float2 f;
        f = __half22float2(*(const __half2*)&v.x); acc[0] += w * f.x; acc[1] += w * f.y;
        f = __half22float2(*(const __half2*)&v.y); acc[2] += w * f.x; acc[3] += w * f.y;
        f = __half22float2(*(const __half2*)&v.z); acc[4] += w * f.x; acc[5] += w * f.y;
        f = __half22float2(*(const __half2*)&v.w); acc[6] += w * f.x; acc[7] += w * f.y;
    }
    #pragma unroll
    for (int i = 0; i < 8; i++) {
        acc[i] += __shfl_xor_sync(0xffffffffu, acc[i], 8);
        acc[i] += __shfl_xor_sync(0xffffffffu, acc[i], 16);
    }
    accw += __shfl_xor_sync(0xffffffffu, accw, 8);
    accw += __shfl_xor_sync(0xffffffffu, accw, 16);

    bool fin = (q == 0) && (ql < 5);       // lanes 0-4 hold cols ql*8..ql*8+7 (40 total)
    float o[8];
    if (fin) {
        float sd = accw;
        const float4* b4 = (const float4*)(bias + ql * 8);
        const float4* t4 = (const float4*)(t + ql * 8);
        float4 b0 = __ldg(b4), b1 = __ldg(b4 + 1);
        float4 t0 = __ldg(t4), t1 = __ldg(t4 + 1);
        o[0] = acc[0] + b0.x + sd * t0.x;
        o[1] = acc[1] + b0.y + sd * t0.y;
        o[2] = acc[2] + b0.z + sd * t0.z;
        o[3] = acc[3] + b0.w + sd * t0.w;
        o[4] = acc[4] + b1.x + sd * t1.x;
        o[5] = acc[5] + b1.y + sd * t1.y;
        o[6] = acc[6] + b1.z + sd * t1.z;
        o[7] = acc[7] + b1.w + sd * t1.w;
        float4* ep = (float4*)(emb + (size_t)wid * 40 + ql * 8);
        ep[0] = make_float4(o[0], o[1], o[2], o[3]);
        ep[1] = make_float4(o[4], o[5], o[6], o[7]);
    }
    float m = -3.4e38f;
    if (fin) {
        #pragma unroll
        for (int i = 0; i < 8; i++) m = fmaxf(m, o[i]);
    }
    #pragma unroll
    for (int od = 16; od > 0; od >>= 1) m = fmaxf(m, __shfl_xor_sync(0xffffffffu, m, od));
    float s = 0.f;
    if (fin) {
        #pragma unroll
        for (int i = 0; i < 8; i++) s += __expf(o[i] - m);
    }
    #pragma unroll
    for (int od = 16; od > 0; od >>= 1) s += __shfl_xor_sync(0xffffffffu, s, od);
    float lse = m + logf(s);
    if (fin) {
        float4* op = (float4*)(out + (size_t)wid * 40 + ql * 8);
        op[0] = make_float4(o[0] - lse, o[1] - lse, o[2] - lse, o[3] - lse);
        op[1] = make_float4(o[4] - lse, o[5] - lse, o[6] - lse, o[7] - lse);
    }
}

// ---------------- fold BN into next layer's weights (reads 32 stat buckets) ----------
template <int NCN>
__global__ void k_fold(const float* __restrict__ W, const float* __restrict__ g,
                       const float* __restrict__ be, const float* __restrict__ st,
                       float* __restrict__ Wf, float* __restrict__ t) {
    __shared__ float a[64], c[64];
    int tid = threadIdx.x;
    __shared__ float red[128];
    if (tid < 128) {
        float v = 0.f;
        #pragma unroll 8
        for (int b = 0; b < 32; b++) v += st[b * 128 + tid];
        red[tid] = v;
    }
    __syncthreads();
    if (tid < 64) {
        float mean = red[tid] * (1.f / NN);
        float var  = red[tid + 64] * (1.f / NN) - mean * mean;
        float ai = g[tid] * rsqrtf(var + EPSV);
        a[tid] = ai;
        c[tid] = be[tid] - mean * ai;
    }
    __syncthreads();
    for (int i = tid; i < 64 * NCN; i += 256) Wf[i] = a[i / NCN] * W[i];
    if (tid < NCN) {
        float tv = 0.f;
        #pragma unroll
        for (int k = 0; k < 64; k++) tv += c[k] * W[k * NCN + tid];
        t[tid] = tv;
    }
}

// ---------------- launcher ----------------
extern "C" void kernel_launch(void* const* d_in, const int* in_sizes, int n_in,
                              void* d_out, int out_size) {
    const float* x   = (const float*)d_in[0];
    const void*  ei  = d_in[1];                 // int32 or int64, detected on device
    const float* W1  = (const float*)d_in[2];
    const float* b1  = (const float*)d_in[3];
    const float* W2  = (const float*)d_in[4];
    const float* b2  = (const float*)d_in[5];
    const float* W3  = (const float*)d_in[6];
    const float* b3  = (const float*)d_in[7];
    const float* g1  = (const float*)d_in[8];
    const float* be1 = (const float*)d_in[9];
    const float* g2  = (const float*)d_in[10];
    const float* be2 = (const float*)d_in[11];
    float* out = (float*)d_out;

    float *hP, *aP, *W2fP, *W3fP, *t2P, *t3P, *z64P, *s1P, *s2P;
    cudaGetSymbolAddress((void**)&hP,   g_h);
    cudaGetSymbolAddress((void**)&aP,   g_agg);
    cudaGetSymbolAddress((void**)&W2fP, g_W2f);
    cudaGetSymbolAddress((void**)&W3fP, g_W3f);
    cudaGetSymbolAddress((void**)&t2P,  g_t2);
    cudaGetSymbolAddress((void**)&t3P,  g_t3);
    cudaGetSymbolAddress((void**)&z64P, g_zero64);
    cudaGetSymbolAddress((void**)&s1P,  g_stats1);
    cudaGetSymbolAddress((void**)&s2P,  g_stats2);

    // output layout: (out, emb) concatenated
    float* emb = (out_size >= 2 * NN * 40) ? (out + NN * 40) : aP;

    // graph build (single stream)
    k_init  <<<(NN + 255) / 256, 256>>>((const long long*)ei);
    k_degree<<<(EE / 4 + 255) / 256, 256>>>(ei);
    k_scanA <<<NT, 256>>>();
    k_scanC <<<NT, 256>>>();
    k_fill  <<<(EE / 4 + NN + 255) / 256, 256>>>(ei);

    // layer 1 (h fp16, agg out fp16, stats fused)
    k_gemm<64, false, true><<<(NN + 63) / 64, 256>>>(x, W1, hP);
    k_agg64h  <<<NN / 8, 256>>>((const uint4*)hP, b1, z64P, (__half*)aP, s1P);
    k_fold<64><<<1, 256>>>(W2, g1, be1, s1P, W2fP, t2P);

    // layer 2 (BN1 folded into W2; fp16 in, fp16 h, fp16 agg out, stats fused)
    k_gemm<64, true, true><<<(NN + 63) / 64, 256>>>(aP, W2fP, hP);
    k_agg64h  <<<NN / 8, 256>>>((const uint4*)hP, b2, t2P, (__half*)aP, s2P);
    k_fold<40><<<1, 256>>>(W3, g2, be2, s2P, W3fP, t3P);

    // layer 3 (BN2 folded into W3; fp16 in, fp16 h padded to 64-half rows)
    // -> quarter-warp fp16 agg + fused log_softmax -> emb, out
    k_gemm<40, true, true><<<(NN + 63) / 64, 160>>>(aP, W3fP, hP);
    k_agg40lsmh<<<(NN + 7) / 8, 256>>>((const uint4*)hP, b3, t3P, emb, out);
}

// round 16
// speedup vs baseline: 1.9090x; 1.2905x over previous
#include <cuda_runtime.h>
#include <cuda_fp16.h>
#include <mma.h>
#include <math.h>

using namespace nvcuda;

#define NN 100000
#define EE 1600000
#define MM (EE + NN)
#define NT 391           // ceil(NN / 256) scan tiles
#define EPSV 1e-5f

// ---------------- scratch (static device allocations; no cudaMalloc) ----------------
__device__ int   g_is64 = 1;        // detection only ever clears -> stable across replays
__device__ int   g_deg[NN];
__device__ float g_dinv[NN];
__device__ int   g_start[NN];
__device__ int   g_cursor[NN];
__device__ int   g_tilesum[NT];
__device__ int2  g_cw[MM];          // (src, norm-bits) per CSR slot
__device__ __align__(16) float g_h[NN * 64];      // fp16 rows, stride 64 halves (2x sized)
__device__ __align__(16) float g_agg[NN * 64];    // fp16 rows, stride 64 halves
__device__ float g_stats1[32 * 128];  // 32 contention buckets x [sum(64), sumsq(64)]
__device__ float g_stats2[32 * 128];
__device__ __align__(16) __half g_W1h[64 * 64];   // W1 in fp16
__device__ __align__(16) __half g_W2h[64 * 64];   // BN1-folded W2, fp16
__device__ __align__(16) __half g_W3h[64 * 64];   // BN2-folded W3, fp16, cols 40-63 = 0
__device__ float g_t2[64];
__device__ __align__(16) float g_t3[64];
__device__ __align__(16) float g_zero64[64];

__device__ __forceinline__ unsigned h2u(__half2 h) {
    return *reinterpret_cast<unsigned*>(&h);
}

// ---------------- graph init + sampled dtype detect + W1 fp16 convert ----------------
__global__ void k_init(const long long* __restrict__ p, const float* __restrict__ W1) {
    int i = blockIdx.x * blockDim.x + threadIdx.x;
    if (i < NN) g_deg[i] = 1;                        // self-loop
    if (i < 32 * 128) { g_stats1[i] = 0.f; g_stats2[i] = 0.f; }
    if (i < 64) g_zero64[i] = 0.f;
    if (i < 64 * 64) g_W1h[i] = __float2half_rn(W1[i]);
    if (i < 8192) {
        long long v = p[(size_t)i * 195];            // max idx < EE int64 slots
        if (v < 0 || v >= NN) g_is64 = 0;            // only writes 0: race-free
    }
}

// ---------------- degree: 4 edges per thread ----------------
__global__ void k_degree(const void* __restrict__ ei) {
    int i = blockIdx.x * blockDim.x + threadIdx.x;
    if (i >= EE / 4) return;
    if (g_is64) {
        const longlong2* p = (const longlong2*)ei;
        longlong2 a = p[EE / 2 + i * 2];
        longlong2 b = p[EE / 2 + i * 2 + 1];
        if ((unsigned long long)a.x < NN) atomicAdd(&g_deg[(int)a.x], 1);
        if ((unsigned long long)a.y < NN) atomicAdd(&g_deg[(int)a.y], 1);
        if ((unsigned long long)b.x < NN) atomicAdd(&g_deg[(int)b.x], 1);
        if ((unsigned long long)b.y < NN) atomicAdd(&g_deg[(int)b.y], 1);
    } else {
        int4 v = ((const int4*)ei)[EE / 4 + i];
        if ((unsigned)v.x < NN) atomicAdd(&g_deg[v.x], 1);
        if ((unsigned)v.y < NN) atomicAdd(&g_deg[v.y], 1);
        if ((unsigned)v.z < NN) atomicAdd(&g_deg[v.z], 1);
        if ((unsigned)v.w < NN) atomicAdd(&g_deg[v.w], 1);
    }
}

// ---------------- scanA: 391 blocks x 256 thr, 1 node/thread + fused dinv ----------
__global__ void k_scanA() {
    int tid = threadIdx.x;
    int idx = blockIdx.x * 256 + tid;
    int d = 0;
    if (idx < NN) {
        d = g_deg[idx];
        g_dinv[idx] = rsqrtf((float)d);
    }
    __shared__ int sh[256];
    sh[tid] = d;
    __syncthreads();
    for (int o = 128; o > 0; o >>= 1) {
        if (tid < o) sh[tid] += sh[tid + o];
        __syncthreads();
    }
    if (tid == 0) g_tilesum[blockIdx.x] = sh[0];
}

// ---------------- scanC: lookback + warp-shuffle scan (2 syncthreads) ----------------
__global__ void k_scanC() {
    int tid = threadIdx.x;
    int lane = tid & 31, wrp = tid >> 5;
    __shared__ int s_off;
    __shared__ int wsum[8];
    if (tid < 32) {
        int v = 0;
        for (int j = tid; j < blockIdx.x; j += 32) v += g_tilesum[j];
        #pragma unroll
        for (int o = 16; o > 0; o >>= 1) v += __shfl_xor_sync(0xffffffffu, v, o);
        if (tid == 0) s_off = v;
    }
    int idx = blockIdx.x * 256 + tid;
    int d = (idx < NN) ? g_deg[idx] : 0;
    int v = d;                           // warp inclusive scan
    #pragma unroll
    for (int o = 1; o < 32; o <<= 1) {
        int u = __shfl_up_sync(0xffffffffu, v, o);
        if (lane >= o) v += u;
    }
    if (lane == 31) wsum[wrp] = v;
    __syncthreads();
    if (tid < 8) {                       // exclusive scan of 8 warp totals
        int x = wsum[tid];
        int y = x;
        #pragma unroll
        for (int o = 1; o < 8; o <<= 1) {
            int u = __shfl_up_sync(0xffu, y, o);
            if (tid >= o) y += u;
        }
        wsum[tid] = y - x;
    }
    __syncthreads();
    if (idx < NN) {
        int p = s_off + wsum[wrp] + v - d;   // exclusive position
        g_start[idx] = p;
        g_cursor[idx] = p;
    }
}

// CSR fill; 4 edges per thread, self-loops appended. (row-sum computed in agg)
__device__ __forceinline__ void fill_one(int s, int d) {
    float w = g_dinv[s] * g_dinv[d];
    int pos = atomicAdd(&g_cursor[d], 1);
    g_cw[pos] = make_int2(s, __float_as_int(w));
}

__global__ void k_fill(const void* __restrict__ ei) {
    int i = blockIdx.x * blockDim.x + threadIdx.x;
    if (i < EE / 4) {
        if (g_is64) {
            const longlong2* p = (const longlong2*)ei;
            longlong2 sa = p[i * 2],           sb = p[i * 2 + 1];
            longlong2 da = p[EE / 2 + i * 2],  db = p[EE / 2 + i * 2 + 1];
            if ((unsigned long long)sa.x < NN && (unsigned long long)da.x < NN)
                fill_one((int)sa.x, (int)da.x);
            if ((unsigned long long)sa.y < NN && (unsigned long long)da.y < NN)
                fill_one((int)sa.y, (int)da.y);
            if ((unsigned long long)sb.x < NN && (unsigned long long)db.x < NN)
                fill_one((int)sb.x, (int)db.x);
            if ((unsigned long long)sb.y < NN && (unsigned long long)db.y < NN)
                fill_one((int)sb.y, (int)db.y);
        } else {
            int4 sv = ((const int4*)ei)[i];
            int4 dv = ((const int4*)ei)[EE / 4 + i];
            if ((unsigned)sv.x < NN && (unsigned)dv.x < NN) fill_one(sv.x, dv.x);
            if ((unsigned)sv.y < NN && (unsigned)dv.y < NN) fill_one(sv.y, dv.y);
            if ((unsigned)sv.z < NN && (unsigned)dv.z < NN) fill_one(sv.z, dv.z);
            if ((unsigned)sv.w < NN && (unsigned)dv.w < NN) fill_one(sv.w, dv.w);
        }
    } else {
        int n = i - EE / 4;
        if (n < NN) fill_one(n, n);        // self-loop
    }
}

// ---------------- tensor-core GEMM: out[N x 64](fp16) = in[N x 64] @ Wh[64 x 64] ----
// Lean HMMA: W pre-converted fp16 (global), A staged once to shared fp16,
// fp32 accumulate, fragments converted to fp16 and stored DIRECTLY to global.
// One __syncthreads total. 64x64 tile, 8 warps (4 row groups x 2 col groups).
template <bool HIN>
__global__ void __launch_bounds__(256)
k_gemm_tc(const void* __restrict__ in, const __half* __restrict__ Wh,
          __half* __restrict__ out) {
    __shared__ __half As[64 * 72];   // ldm 72 halves (144B rows, 16B-aligned)
    __shared__ __half Bs[64 * 72];
    int tid = threadIdx.x;
    int row0 = blockIdx.x * 64;

    // stage W (fp16 global -> shared), 512 uint4
    for (int i = tid; i < 512; i += 256) {
        int k = i >> 3, c8 = i & 7;
        *(uint4*)&Bs[k * 72 + c8 * 8] = ((const uint4*)Wh)[i];
    }
    // stage A rows (convert if fp32 input)
    for (int i = tid; i < 512; i += 256) {
        int r = i >> 3, c8 = i & 7;
        int gr = row0 + r;
        uint4 v = make_uint4(0u, 0u, 0u, 0u);
        if (gr < NN) {
            if (HIN) {
                v = *(const uint4*)((const __half*)in + (size_t)gr * 64 + c8 * 8);
            } else {
                const float4* f4 = (const float4*)((const float*)in + (size_t)gr * 64 + c8 * 8);
                float4 f0 = f4[0], f1 = f4[1];
                v.x = h2u(__floats2half2_rn(f0.x, f0.y));
                v.y = h2u(__floats2half2_rn(f0.z, f0.w));
                v.z = h2u(__floats2half2_rn(f1.x, f1.y));
                v.w = h2u(__floats2half2_rn(f1.z, f1.w));
            }
        }
        *(uint4*)&As[r * 72 + c8 * 8] = v;
    }
    __syncthreads();

    int wid = tid >> 5;
    int wr = wid >> 1, wc = wid & 1;     // 4 row groups x 2 col groups (16x32 each)
    wmma::fragment<wmma::accumulator, 16, 16, 16, float> c0, c1;
    wmma::fill_fragment(c0, 0.f);
    wmma::fill_fragment(c1, 0.f);
    #pragma unroll
    for (int kk = 0; kk < 4; kk++) {
        wmma::fragment<wmma::matrix_a, 16, 16, 16, __half, wmma::row_major> a;
        wmma::load_matrix_sync(a, &As[wr * 16 * 72 + kk * 16], 72);
        wmma::fragment<wmma::matrix_b, 16, 16, 16, __half, wmma::row_major> b;
        wmma::load_matrix_sync(b, &Bs[kk * 16 * 72 + wc * 32], 72);
        wmma::mma_sync(c0, a, b, c0);
        wmma::load_matrix_sync(b, &Bs[kk * 16 * 72 + wc * 32 + 16], 72);
        wmma::mma_sync(c1, a, b, c1);
    }
    // convert fp32 accum -> fp16 accum fragments (same-shape elementwise map)
    wmma::fragment<wmma::accumulator, 16, 16, 16, __half> h0, h1;
    #pragma unroll
    for (int i = 0; i < c0.num_elements; i++) {
        h0.x[i] = __float2half_rn(c0.x[i]);
        h1.x[i] = __float2half_rn(c1.x[i]);
    }
    // direct global store (tail rows land inside the 2x-sized buffer)
    __half* op = out + (size_t)(row0 + wr * 16) * 64 + wc * 32;
    wmma::store_matrix_sync(op, h0, 64, wmma::mem_row_major);
    wmma::store_matrix_sync(op + 16, h1, 64, wmma::mem_row_major);
}

// ---------------- aggregation (NC=64, fp16 h) + fused BN stats, fp16 output --------
__global__ void __launch_bounds__(256)
k_agg64h(const uint4* __restrict__ h4, const float* __restrict__ bias,
         const float* __restrict__ t, __half* __restrict__ out,
         float* __restrict__ st) {
    __shared__ float s_sum[8][64];
    __shared__ float s_sq[8][64];
    int tid = threadIdx.x;
    int wIdx = tid >> 5;
    int wid  = blockIdx.x * 8 + wIdx;      // always < NN
    int lane = tid & 31;
    int q = lane >> 3, ql = lane & 7;
    int stt = g_start[wid], en = stt + g_deg[wid];
    float acc[8];
    float accw = 0.f;                      // row-sum of norms
    #pragma unroll
    for (int i = 0; i < 8; i++) acc[i] = 0.f;

    #pragma unroll 2
    for (int e = stt + q; e < en; e += 4) {
        int2 c = __ldg(&g_cw[e]);
        uint4 v = __ldg(h4 + (size_t)c.x * 8 + ql);   // 8 halves of the row
        float w = __int_as_float(c.y);
        accw += w;
        float2 f;
        f = __half22float2(*(const __half2*)&v.x); acc[0] += w * f.x; acc[1] += w * f.y;
        f = __half22float2(*(const __half2*)&v.y); acc[2] += w * f.x; acc[3] += w * f.y;
        f = __half22float2(*(const __half2*)&v.z); acc[4] += w * f.x; acc[5] += w * f.y;
        f = __half22float2(*(const __half2*)&v.w); acc[6] += w * f.x; acc[7] += w * f.y;
    }
    #pragma unroll
    for (int i = 0; i < 8; i++) {
        acc[i] += __shfl_xor_sync(0xffffffffu, acc[i], 8);
        acc[i] += __shfl_xor_sync(0xffffffffu, acc[i], 16);
    }
    accw += __shfl_xor_sync(0xffffffffu, accw, 8);
    accw += __shfl_xor_sync(0xffffffffu, accw, 16);
    if (q == 0) {   // lanes 0-7 hold full sums for cols ql*8 .. ql*8+7
        float sd = accw;
        const float4* b4 = (const float4*)(bias + ql * 8);
        const float4* t4 = (const float4*)(t + ql * 8);
        float4 b0 = __ldg(b4), b1 = __ldg(b4 + 1);
        float4 t0 = __ldg(t4), t1 = __ldg(t4 + 1);
        float o[8];
        o[0] = acc[0] + b0.x + sd * t0.x;
        o[1] = acc[1] + b0.y + sd * t0.y;
        o[2] = acc[2] + b0.z + sd * t0.z;
        o[3] = acc[3] + b0.w + sd * t0.w;
        o[4] = acc[4] + b1.x + sd * t1.x;
        o[5] = acc[5] + b1.y + sd * t1.y;
        o[6] = acc[6] + b1.z + sd * t1.z;
        o[7] = acc[7] + b1.w + sd * t1.w;
        uint4 pk;
        pk.x = h2u(__floats2half2_rn(o[0], o[1]));
        pk.y = h2u(__floats2half2_rn(o[2], o[3]));
        pk.z = h2u(__floats2half2_rn(o[4], o[5]));
        pk.w = h2u(__floats2half2_rn(o[6], o[7]));
        *(uint4*)(out + (size_t)wid * 64 + ql * 8) = pk;
        #pragma unroll
        for (int i = 0; i < 8; i++) {
            s_sum[wIdx][ql * 8 + i] = o[i];
            s_sq [wIdx][ql * 8 + i] = o[i] * o[i];
        }
    }
    __syncthreads();
    if (tid < 64) {
        float a = 0.f, b = 0.f;
        #pragma unroll
        for (int w = 0; w < 8; w++) { a += s_sum[w][tid]; b += s_sq[w][tid]; }
        int bkt = (blockIdx.x & 31) * 128;
        atomicAdd(&st[bkt + tid], a);
        atomicAdd(&st[bkt + tid + 64], b);
    }
}

// ---------------- layer-3 aggregation (fp16 h, 40 valid cols of 64) + log_softmax ----
// Cols 40-63 are exact zeros (W3h zero-padded); accumulated then discarded.
__global__ void k_agg40lsmh(const uint4* __restrict__ h4, const float* __restrict__ bias,
                            const float* __restrict__ t, float* __restrict__ emb,
                            float* __restrict__ out) {
    int wid  = (blockIdx.x * blockDim.x + threadIdx.x) >> 5;
    int lane = threadIdx.x & 31;
    if (wid >= NN) return;
    int q = lane >> 3, ql = lane & 7;
    int stt = g_start[wid], en = stt + g_deg[wid];
    float acc[8];
    float accw = 0.f;
    #pragma unroll
    for (int i = 0; i < 8; i++) acc[i] = 0.f;

    #pragma unroll 2
    for (int e = stt + q; e < en; e += 4) {
        int2 c = __ldg(&g_cw[e]);
        uint4 v = __ldg(h4 + (size_t)c.x * 8 + ql);
        float w = __int_as_float(c.y);
        accw += w;
        float2 f;
        f = __half22float2(*(const __half2*)&v.x); acc[0] += w * f.x; acc[1] += w * f.y;
        f = __half22float2(*(const __half2*)&v.y); acc[2] += w * f.x; acc[3] += w * f.y;
        f = __half22float2(*(const __half2*)&v.z); acc[4] += w * f.x; acc[5] += w * f.y;
        f = __half22float2(*(const __half2*)&v.w); acc[6] += w * f.x; acc[7] += w * f.y;
    }
    #pragma unroll
    for (int i = 0; i < 8; i++) {
        acc[i] += __shfl_xor_sync(0xffffffffu, acc[i], 8);
        acc[i] += __shfl_xor_sync(0xffffffffu, acc[i], 16);
    }
    accw += __shfl_xor_sync(0xffffffffu, accw, 8);
    accw += __shfl_xor_sync(0xffffffffu, accw, 16);

    bool fin = (q == 0) && (ql < 5);       // lanes 0-4 hold cols ql*8..ql*8+7 (40 total)
    float o[8];
    if (fin) {
        float sd = accw;
        const float4* b4 = (const float4*)(bias + ql * 8);
        const float4* t4 = (const float4*)(t + ql * 8);
        float4 b0 = __ldg(b4), b1 = __ldg(b4 + 1);
        float4 t0 = __ldg(t4), t1 = __ldg(t4 + 1);
        o[0] = acc[0] + b0.x + sd * t0.x;
        o[1] = acc[1] + b0.y + sd * t0.y;
        o[2] = acc[2] + b0.z + sd * t0.z;
        o[3] = acc[3] + b0.w + sd * t0.w;
        o[4] = acc[4] + b1.x + sd * t1.x;
        o[5] = acc[5] + b1.y + sd * t1.y;
        o[6] = acc[6] + b1.z + sd * t1.z;
        o[7] = acc[7] + b1.w + sd * t1.w;
        float4* ep = (float4*)(emb + (size_t)wid * 40 + ql * 8);
        ep[0] = make_float4(o[0], o[1], o[2], o[3]);
        ep[1] = make_float4(o[4], o[5], o[6], o[7]);
    }
    float m = -3.4e38f;
    if (fin) {
        #pragma unroll
        for (int i = 0; i < 8; i++) m = fmaxf(m, o[i]);
    }
    #pragma unroll
    for (int od = 16; od > 0; od >>= 1) m = fmaxf(m, __shfl_xor_sync(0xffffffffu, m, od));
    float s = 0.f;
    if (fin) {
        #pragma unroll
        for (int i = 0; i < 8; i++) s += __expf(o[i] - m);
    }
    #pragma unroll
    for (int od = 16; od > 0; od >>= 1) s += __shfl_xor_sync(0xffffffffu, s, od);
    float lse = m + logf(s);
    if (fin) {
        float4* op = (float4*)(out + (size_t)wid * 40 + ql * 8);
        op[0] = make_float4(o[0] - lse, o[1] - lse, o[2] - lse, o[3] - lse);
        op[1] = make_float4(o[4] - lse, o[5] - lse, o[6] - lse, o[7] - lse);
    }
}

// ---------------- fold BN into next layer's weights -> fp16 Wf (zero-padded) --------
template <int NCN>
__global__ void k_fold(const float* __restrict__ W, const float* __restrict__ g,
                       const float* __restrict__ be, const float* __restrict__ st,
                       __half* __restrict__ Wf, float* __restrict__ t) {
    __shared__ float a[64], c[64];
    int tid = threadIdx.x;
    __shared__ float red[128];
    if (tid < 128) {
        float v = 0.f;
        #pragma unroll 8
        for (int b = 0; b < 32; b++) v += st[b * 128 + tid];
        red[tid] = v;
    }
    __syncthreads();
    if (tid < 64) {
        float mean = red[tid] * (1.f / NN);
        float var  = red[tid + 64] * (1.f / NN) - mean * mean;
        float ai = g[tid] * rsqrtf(var + EPSV);
        a[tid] = ai;
        c[tid] = be[tid] - mean * ai;
    }
    __syncthreads();
    for (int i = tid; i < 64 * 64; i += 256) {
        int k = i >> 6, j = i & 63;
        float v = (j < NCN) ? a[k] * W[k * NCN + j] : 0.f;
        Wf[i] = __float2half_rn(v);
    }
    if (tid < NCN) {
        float tv = 0.f;
        #pragma unroll
        for (int k = 0; k < 64; k++) tv += c[k] * W[k * NCN + tid];
        t[tid] = tv;
    }
}

// ---------------- launcher ----------------
extern "C" void kernel_launch(void* const* d_in, const int* in_sizes, int n_in,
                              void* d_out, int out_size) {
    const float* x   = (const float*)d_in[0];
    const void*  ei  = d_in[1];                 // int32 or int64, detected on device
    const float* W1  = (const float*)d_in[2];
    const float* b1  = (const float*)d_in[3];
    const float* W2  = (const float*)d_in[4];
    const float* b2  = (const float*)d_in[5];
    const float* W3  = (const float*)d_in[6];
    const float* b3  = (const float*)d_in[7];
    const float* g1  = (const float*)d_in[8];
    const float* be1 = (const float*)d_in[9];
    const float* g2  = (const float*)d_in[10];
    const float* be2 = (const float*)d_in[11];
    float* out = (float*)d_out;

    float *hP, *aP, *t2P, *t3P, *z64P, *s1P, *s2P;
    __half *W1hP, *W2hP, *W3hP;
    cudaGetSymbolAddress((void**)&hP,   g_h);
    cudaGetSymbolAddress((void**)&aP,   g_agg);
    cudaGetSymbolAddress((void**)&W1hP, g_W1h);
    cudaGetSymbolAddress((void**)&W2hP, g_W2h);
    cudaGetSymbolAddress((void**)&W3hP, g_W3h);
    cudaGetSymbolAddress((void**)&t2P,  g_t2);
    cudaGetSymbolAddress((void**)&t3P,  g_t3);
    cudaGetSymbolAddress((void**)&z64P, g_zero64);
    cudaGetSymbolAddress((void**)&s1P,  g_stats1);
    cudaGetSymbolAddress((void**)&s2P,  g_stats2);

    // output layout: (out, emb) concatenated
    float* emb = (out_size >= 2 * NN * 40) ? (out + NN * 40) : aP;

    // graph build (single stream)
    k_init  <<<NT, 256>>>((const long long*)ei, W1);
    k_degree<<<(EE / 4 + 255) / 256, 256>>>(ei);
    k_scanA <<<NT, 256>>>();
    k_scanC <<<NT, 256>>>();
    k_fill  <<<(EE / 4 + NN + 255) / 256, 256>>>(ei);

    // layer 1 (tensor-core GEMM, h fp16, agg out fp16, stats fused)
    k_gemm_tc<false><<<(NN + 63) / 64, 256>>>(x, W1hP, (__half*)hP);
    k_agg64h  <<<NN / 8, 256>>>((const uint4*)hP, b1, z64P, (__half*)aP, s1P);
    k_fold<64><<<1, 256>>>(W2, g1, be1, s1P, W2hP, t2P);

    // layer 2 (BN1 folded into W2h; fp16 throughout, stats fused)
    k_gemm_tc<true><<<(NN + 63) / 64, 256>>>(aP, W2hP, (__half*)hP);
    k_agg64h  <<<NN / 8, 256>>>((const uint4*)hP, b2, t2P, (__half*)aP, s2P);
    k_fold<40><<<1, 256>>>(W3, g2, be2, s2P, W3hP, t3P);

    // layer 3 (BN2 folded into W3h, zero-padded to 64 cols; fp16 h)
    // -> quarter-warp fp16 agg + fused log_softmax -> emb, out
    k_gemm_tc<true><<<(NN + 63) / 64, 256>>>(aP, W3hP, (__half*)hP);
    k_agg40lsmh<<<(NN + 7) / 8, 256>>>((const uint4*)hP, b3, t3P, emb, out);
}